// round 1
// baseline (speedup 1.0000x reference)
#include <cuda_runtime.h>
#include <cuda_bf16.h>
#include <math.h>

// Problem constants
#define BB   4
#define SS   2048
#define DD   1024
#define NH   16
#define NKV  4
#define DK   64
#define NG   (NH / NKV)   // 4

// -------- scratch (no allocations allowed) --------
__device__ float g_q[BB * SS * NH * DK];    // [B,S,NH,DK]  32 MB
__device__ float g_k[BB * SS * NKV * DK];   // [B,S,NKV,DK]  8 MB
__device__ float g_v[BB * SS * NKV * DK];   //               8 MB
__device__ float g_ctx[BB * SS * DD];       // [B,S,NH,DK]  32 MB

// ============================================================
// SGEMM: C[M,N] = A[M,K] @ B[K,N], fp32, 64x64 tile, BK=16,
// 256 threads, 4x4 micro-tile. M,N,K divisible by tile sizes.
// ============================================================
__global__ __launch_bounds__(256) void sgemm64(
    const float* __restrict__ A, const float* __restrict__ B,
    float* __restrict__ C, int M, int N, int K)
{
    __shared__ __align__(16) float As[16][68];  // transposed, padded
    __shared__ __align__(16) float Bs[16][64];

    const int tid = threadIdx.x;
    const int tx  = tid & 15;        // 0..15 -> col group
    const int ty  = tid >> 4;        // 0..15 -> row group
    const int rowBase = blockIdx.y * 64;
    const int colBase = blockIdx.x * 64;

    // load mapping (float4 per thread per tile)
    const int aRow = (tid * 4) >> 4;   // 0..63
    const int aCol = (tid * 4) & 15;   // 0,4,8,12
    const int bRow = (tid * 4) >> 6;   // 0..15
    const int bCol = (tid * 4) & 63;

    float acc[4][4];
#pragma unroll
    for (int i = 0; i < 4; i++)
#pragma unroll
        for (int j = 0; j < 4; j++) acc[i][j] = 0.0f;

    for (int k0 = 0; k0 < K; k0 += 16) {
        float4 a4 = *(const float4*)(A + (size_t)(rowBase + aRow) * K + (k0 + aCol));
        float4 b4 = *(const float4*)(B + (size_t)(k0 + bRow) * N + (colBase + bCol));
        As[aCol + 0][aRow] = a4.x;
        As[aCol + 1][aRow] = a4.y;
        As[aCol + 2][aRow] = a4.z;
        As[aCol + 3][aRow] = a4.w;
        *(float4*)&Bs[bRow][bCol] = b4;
        __syncthreads();

#pragma unroll
        for (int kk = 0; kk < 16; kk++) {
            float4 av = *(const float4*)&As[kk][ty * 4];
            float4 bv = *(const float4*)&Bs[kk][tx * 4];
            float a[4] = {av.x, av.y, av.z, av.w};
            float b[4] = {bv.x, bv.y, bv.z, bv.w};
#pragma unroll
            for (int i = 0; i < 4; i++)
#pragma unroll
                for (int j = 0; j < 4; j++)
                    acc[i][j] = fmaf(a[i], b[j], acc[i][j]);
        }
        __syncthreads();
    }

#pragma unroll
    for (int i = 0; i < 4; i++) {
        float4 out = make_float4(acc[i][0], acc[i][1], acc[i][2], acc[i][3]);
        *(float4*)(C + (size_t)(rowBase + ty * 4 + i) * N + (colBase + tx * 4)) = out;
    }
}

// ============================================================
// RoPE, in place. t layout: [B*S, H, 64]. One thread per (row, i<32).
// ============================================================
__global__ void rope_kernel(float* __restrict__ t, int total, int H)
{
    int idx = blockIdx.x * blockDim.x + threadIdx.x;
    if (idx >= total) return;
    int i  = idx & 31;
    int rh = idx >> 5;            // (b*S+s)*H + h
    int s  = (rh / H) % SS;

    float inv_freq = powf(10000.0f, -(float)i / 32.0f);
    float ang = (float)s * inv_freq;
    float c, sn;
    sincosf(ang, &sn, &c);

    float* p = t + (size_t)rh * 64 + i;
    float a  = p[0];
    float b  = p[32];
    p[0]  = a * c - b * sn;
    p[32] = b * c + a * sn;
}

// ============================================================
// Causal GQA flash attention.
// grid: (S/128, NH, B); block: 128 threads, 1 thread = 1 query row.
// Q/acc in registers, 64-key K/V tiles in smem (broadcast reads).
// ============================================================
__global__ __launch_bounds__(128) void flash_kernel(
    const float* __restrict__ Q, const float* __restrict__ K,
    const float* __restrict__ V, float* __restrict__ O)
{
    const int tid  = threadIdx.x;
    const int qpos = blockIdx.x * 128 + tid;
    const int h    = blockIdx.y;
    const int b    = blockIdx.z;
    const int kvh  = h / NG;

    __shared__ __align__(16) float4 Ks[72][16];  // 64 rows + pad for masked OOB reads
    __shared__ __align__(16) float4 Vs[72][16];

    const float4* Q4 = (const float4*)Q;
    const float4* K4 = (const float4*)K;
    const float4* V4 = (const float4*)V;

    float4 qv[16];
    {
        size_t qbase = ((size_t)(b * SS + qpos) * NH + h) * 16;
#pragma unroll
        for (int i = 0; i < 16; i++) qv[i] = Q4[qbase + i];
    }

    float4 acc[16];
#pragma unroll
    for (int i = 0; i < 16; i++) acc[i] = make_float4(0.f, 0.f, 0.f, 0.f);
    float m = -1e30f, l = 0.0f;

    const int kend = blockIdx.x * 128 + 128;   // same for all threads of block

    for (int ktb = 0; ktb < kend; ktb += 64) {
        __syncthreads();
        // cooperative load of 64 K rows and 64 V rows (16 float4 each)
        for (int i = tid; i < 64 * 16; i += 128) {
            int row = i >> 4, col = i & 15;
            size_t src = ((size_t)(b * SS + (ktb + row)) * NKV + kvh) * 16 + col;
            Ks[row][col] = K4[src];
            Vs[row][col] = V4[src];
        }
        __syncthreads();

        int jmax = qpos - ktb + 1;
        if (jmax > 64) jmax = 64;
        // jmax may be <=0 for threads whose query is before this tile? No:
        // ktb < kend = blockbase+128 and qpos >= blockbase, so jmax >= blockbase-ktb+1.
        // Worst case ktb = blockbase+64 (diagonal second half): jmax >= -63 -> can be <=0.
        for (int c = 0; c < jmax; c += 8) {
            float sc[8];
#pragma unroll
            for (int jj = 0; jj < 8; jj++) {
                int j = c + jj;
                float s = 0.f;
#pragma unroll
                for (int i = 0; i < 16; i++) {
                    float4 kk = Ks[j][i];
                    s = fmaf(qv[i].x, kk.x, s);
                    s = fmaf(qv[i].y, kk.y, s);
                    s = fmaf(qv[i].z, kk.z, s);
                    s = fmaf(qv[i].w, kk.w, s);
                }
                sc[jj] = (j < jmax) ? s * 0.125f : -1e30f;
            }
            float mnew = m;
#pragma unroll
            for (int jj = 0; jj < 8; jj++) mnew = fmaxf(mnew, sc[jj]);
            float corr = __expf(m - mnew);
            m = mnew;
            float p[8];
            float psum = 0.f;
#pragma unroll
            for (int jj = 0; jj < 8; jj++) {
                p[jj] = __expf(sc[jj] - mnew);
                psum += p[jj];
            }
            l = l * corr + psum;
#pragma unroll
            for (int i = 0; i < 16; i++) {
                float4 a = acc[i];
                a.x *= corr; a.y *= corr; a.z *= corr; a.w *= corr;
#pragma unroll
                for (int jj = 0; jj < 8; jj++) {
                    float4 vv = Vs[c + jj][i];
                    a.x = fmaf(p[jj], vv.x, a.x);
                    a.y = fmaf(p[jj], vv.y, a.y);
                    a.z = fmaf(p[jj], vv.z, a.z);
                    a.w = fmaf(p[jj], vv.w, a.w);
                }
                acc[i] = a;
            }
        }
    }

    float invl = 1.0f / l;
    float4* O4 = (float4*)O;
    size_t obase = ((size_t)(b * SS + qpos) * NH + h) * 16;
#pragma unroll
    for (int i = 0; i < 16; i++) {
        float4 a = acc[i];
        a.x *= invl; a.y *= invl; a.z *= invl; a.w *= invl;
        O4[obase + i] = a;
    }
}

// ============================================================
// launch
// ============================================================
extern "C" void kernel_launch(void* const* d_in, const int* in_sizes, int n_in,
                              void* d_out, int out_size)
{
    const float* x  = (const float*)d_in[0];
    const float* Wq = (const float*)d_in[1];
    const float* Wk = (const float*)d_in[2];
    const float* Wv = (const float*)d_in[3];
    const float* Wo = (const float*)d_in[4];
    // d_in[5] = causal mask, known statically -> ignored
    float* out = (float*)d_out;

    float *q, *k, *v, *ctx;
    cudaGetSymbolAddress((void**)&q,   g_q);
    cudaGetSymbolAddress((void**)&k,   g_k);
    cudaGetSymbolAddress((void**)&v,   g_v);
    cudaGetSymbolAddress((void**)&ctx, g_ctx);

    const int M = BB * SS;  // 8192

    // QKV projections
    sgemm64<<<dim3((NH * DK) / 64, M / 64), 256>>>(x, Wq, q, M, NH * DK, DD);
    sgemm64<<<dim3((NKV * DK) / 64, M / 64), 256>>>(x, Wk, k, M, NKV * DK, DD);
    sgemm64<<<dim3((NKV * DK) / 64, M / 64), 256>>>(x, Wv, v, M, NKV * DK, DD);

    // RoPE on q and k
    {
        int nq = M * NH * 32;
        rope_kernel<<<(nq + 255) / 256, 256>>>(q, nq, NH);
        int nk = M * NKV * 32;
        rope_kernel<<<(nk + 255) / 256, 256>>>(k, nk, NKV);
    }

    // causal GQA attention
    flash_kernel<<<dim3(SS / 128, NH, BB), 128>>>(q, k, v, ctx);

    // output projection
    sgemm64<<<dim3(DD / 64, M / 64), 256>>>(ctx, Wo, out, M, DD, DD);
}

// round 2
// speedup vs baseline: 1.4405x; 1.4405x over previous
#include <cuda_runtime.h>
#include <cuda_bf16.h>
#include <math.h>
#include <stdint.h>

// Problem constants
#define BB   4
#define SS   2048
#define DD   1024
#define NH   16
#define NKV  4
#define DK   64
#define NG   (NH / NKV)   // 4

// -------- scratch (no allocations allowed) --------
__device__ float g_q[BB * SS * NH * DK];    // [B,S,NH,DK]  32 MB
__device__ float g_k[BB * SS * NKV * DK];   // [B,S,NKV,DK]  8 MB
__device__ float g_v[BB * SS * NKV * DK];   //               8 MB
__device__ float g_ctx[BB * SS * DD];       // [B,S,NH,DK]  32 MB

// ============================================================
// TF32 tensor-core GEMM: C[M,N] = A[M,K] @ B[K,N]
// 128x128x32 tiles, 256 threads, warp tile 64x32 (m16n8k8 atoms)
// ============================================================
__device__ __forceinline__ float tf32r(float x) {
    uint32_t u;
    asm("cvt.rna.tf32.f32 %0, %1;" : "=r"(u) : "f"(x));
    return __uint_as_float(u);
}

#define AS_STRIDE 36   // BK(32) + 4 pad  -> frag banks (4*lr+lc)%32 all distinct
#define BS_STRIDE 136  // BN(128) + 8 pad -> frag banks (8*lc+lr)%32 all distinct

__global__ __launch_bounds__(256) void gemm_tf32(
    const float* __restrict__ A, const float* __restrict__ B,
    float* __restrict__ C, int M, int N, int K)
{
    __shared__ __align__(16) float As[128 * AS_STRIDE];
    __shared__ __align__(16) float Bs[32 * BS_STRIDE];

    const int tid  = threadIdx.x;
    const int warp = tid >> 5;
    const int lane = tid & 31;
    const int lr   = lane >> 2;   // 0..7
    const int lc   = lane & 3;    // 0..3
    const int wrow = (warp & 1) * 64;
    const int wcol = (warp >> 1) * 32;
    const long rowBase = (long)blockIdx.y * 128;
    const long colBase = (long)blockIdx.x * 128;

    // global->smem load mapping
    const int arow = tid >> 1;          // 0..127 (2 threads per A row)
    const int af4  = (tid & 1) * 4;     // float4 col group base
    const int brow = tid >> 3;          // 0..31  (8 threads per B row)
    const int bf4  = tid & 7;           // float4 col base (+8i)

    const float* Aptr = A + (rowBase + arow) * (long)K + af4 * 4;
    const float* Bptr = B + (long)brow * N + colBase + bf4 * 4;

    float acc[4][4][4];
#pragma unroll
    for (int i = 0; i < 4; i++)
#pragma unroll
        for (int j = 0; j < 4; j++)
#pragma unroll
            for (int r = 0; r < 4; r++) acc[i][j][r] = 0.0f;

    float4 ra[4], rb[4];

    // prologue: tile 0
#pragma unroll
    for (int i = 0; i < 4; i++) ra[i] = *(const float4*)(Aptr + i * 4);
#pragma unroll
    for (int i = 0; i < 4; i++) rb[i] = *(const float4*)(Bptr + i * 32);

#pragma unroll
    for (int i = 0; i < 4; i++) {
        float4 t = ra[i];
        t.x = tf32r(t.x); t.y = tf32r(t.y); t.z = tf32r(t.z); t.w = tf32r(t.w);
        *(float4*)&As[arow * AS_STRIDE + af4 * 4 + i * 4] = t;
        float4 u = rb[i];
        u.x = tf32r(u.x); u.y = tf32r(u.y); u.z = tf32r(u.z); u.w = tf32r(u.w);
        *(float4*)&Bs[brow * BS_STRIDE + bf4 * 4 + i * 32] = u;
    }
    __syncthreads();

    for (int k0 = 32;; k0 += 32) {
        const bool more = (k0 < K);
        if (more) {
#pragma unroll
            for (int i = 0; i < 4; i++) ra[i] = *(const float4*)(Aptr + k0 + i * 4);
#pragma unroll
            for (int i = 0; i < 4; i++) rb[i] = *(const float4*)(Bptr + (long)k0 * N + i * 32);
        }

        // compute on current smem tile
        const uint32_t* Au = (const uint32_t*)As;
        const uint32_t* Bu = (const uint32_t*)Bs;
#pragma unroll
        for (int ks = 0; ks < 4; ks++) {
            const int kk = ks * 8;
            uint32_t a[4][4], b[4][2];
#pragma unroll
            for (int ma = 0; ma < 4; ma++) {
                int r = wrow + ma * 16 + lr;
                a[ma][0] = Au[r * AS_STRIDE + kk + lc];
                a[ma][1] = Au[(r + 8) * AS_STRIDE + kk + lc];
                a[ma][2] = Au[r * AS_STRIDE + kk + lc + 4];
                a[ma][3] = Au[(r + 8) * AS_STRIDE + kk + lc + 4];
            }
#pragma unroll
            for (int na = 0; na < 4; na++) {
                int c = wcol + na * 8 + lr;
                b[na][0] = Bu[(kk + lc) * BS_STRIDE + c];
                b[na][1] = Bu[(kk + lc + 4) * BS_STRIDE + c];
            }
#pragma unroll
            for (int ma = 0; ma < 4; ma++)
#pragma unroll
                for (int na = 0; na < 4; na++) {
                    asm volatile(
                        "mma.sync.aligned.m16n8k8.row.col.f32.tf32.tf32.f32 "
                        "{%0,%1,%2,%3}, {%4,%5,%6,%7}, {%8,%9}, {%0,%1,%2,%3};\n"
                        : "+f"(acc[ma][na][0]), "+f"(acc[ma][na][1]),
                          "+f"(acc[ma][na][2]), "+f"(acc[ma][na][3])
                        : "r"(a[ma][0]), "r"(a[ma][1]), "r"(a[ma][2]), "r"(a[ma][3]),
                          "r"(b[na][0]), "r"(b[na][1]));
                }
        }

        if (!more) break;
        __syncthreads();
#pragma unroll
        for (int i = 0; i < 4; i++) {
            float4 t = ra[i];
            t.x = tf32r(t.x); t.y = tf32r(t.y); t.z = tf32r(t.z); t.w = tf32r(t.w);
            *(float4*)&As[arow * AS_STRIDE + af4 * 4 + i * 4] = t;
            float4 u = rb[i];
            u.x = tf32r(u.x); u.y = tf32r(u.y); u.z = tf32r(u.z); u.w = tf32r(u.w);
            *(float4*)&Bs[brow * BS_STRIDE + bf4 * 4 + i * 32] = u;
        }
        __syncthreads();
    }

    // epilogue
#pragma unroll
    for (int ma = 0; ma < 4; ma++) {
#pragma unroll
        for (int na = 0; na < 4; na++) {
            long r = rowBase + wrow + ma * 16 + lr;
            long c = colBase + wcol + na * 8 + 2 * lc;
            *(float2*)(C + r * N + c)       = make_float2(acc[ma][na][0], acc[ma][na][1]);
            *(float2*)(C + (r + 8) * N + c) = make_float2(acc[ma][na][2], acc[ma][na][3]);
        }
    }
}

// ============================================================
// RoPE, in place. t layout: [B*S, H, 64]. One thread per (row, i<32).
// ============================================================
__global__ void rope_kernel(float* __restrict__ t, int total, int H)
{
    int idx = blockIdx.x * blockDim.x + threadIdx.x;
    if (idx >= total) return;
    int i  = idx & 31;
    int rh = idx >> 5;            // (b*S+s)*H + h
    int s  = (rh / H) % SS;

    float inv_freq = powf(10000.0f, -(float)i / 32.0f);
    float ang = (float)s * inv_freq;
    float c, sn;
    sincosf(ang, &sn, &c);

    float* p = t + (size_t)rh * 64 + i;
    float a  = p[0];
    float b  = p[32];
    p[0]  = a * c - b * sn;
    p[32] = b * c + a * sn;
}

// ============================================================
// Causal GQA flash attention (fp32, 1 thread = 1 query row).
// ============================================================
__global__ __launch_bounds__(128) void flash_kernel(
    const float* __restrict__ Q, const float* __restrict__ K,
    const float* __restrict__ V, float* __restrict__ O)
{
    const int tid  = threadIdx.x;
    const int qpos = blockIdx.x * 128 + tid;
    const int h    = blockIdx.y;
    const int b    = blockIdx.z;
    const int kvh  = h / NG;

    __shared__ __align__(16) float4 Ks[72][16];
    __shared__ __align__(16) float4 Vs[72][16];

    const float4* Q4 = (const float4*)Q;
    const float4* K4 = (const float4*)K;
    const float4* V4 = (const float4*)V;

    float4 qv[16];
    {
        size_t qbase = ((size_t)(b * SS + qpos) * NH + h) * 16;
#pragma unroll
        for (int i = 0; i < 16; i++) qv[i] = Q4[qbase + i];
    }

    float4 acc[16];
#pragma unroll
    for (int i = 0; i < 16; i++) acc[i] = make_float4(0.f, 0.f, 0.f, 0.f);
    float m = -1e30f, l = 0.0f;

    const int kend = blockIdx.x * 128 + 128;

    for (int ktb = 0; ktb < kend; ktb += 64) {
        __syncthreads();
        for (int i = tid; i < 64 * 16; i += 128) {
            int row = i >> 4, col = i & 15;
            size_t src = ((size_t)(b * SS + (ktb + row)) * NKV + kvh) * 16 + col;
            Ks[row][col] = K4[src];
            Vs[row][col] = V4[src];
        }
        __syncthreads();

        int jmax = qpos - ktb + 1;
        if (jmax > 64) jmax = 64;
        for (int c = 0; c < jmax; c += 8) {
            float sc[8];
#pragma unroll
            for (int jj = 0; jj < 8; jj++) {
                int j = c + jj;
                float s = 0.f;
#pragma unroll
                for (int i = 0; i < 16; i++) {
                    float4 kk = Ks[j][i];
                    s = fmaf(qv[i].x, kk.x, s);
                    s = fmaf(qv[i].y, kk.y, s);
                    s = fmaf(qv[i].z, kk.z, s);
                    s = fmaf(qv[i].w, kk.w, s);
                }
                sc[jj] = (j < jmax) ? s * 0.125f : -1e30f;
            }
            float mnew = m;
#pragma unroll
            for (int jj = 0; jj < 8; jj++) mnew = fmaxf(mnew, sc[jj]);
            float corr = __expf(m - mnew);
            m = mnew;
            float p[8];
            float psum = 0.f;
#pragma unroll
            for (int jj = 0; jj < 8; jj++) {
                p[jj] = __expf(sc[jj] - mnew);
                psum += p[jj];
            }
            l = l * corr + psum;
#pragma unroll
            for (int i = 0; i < 16; i++) {
                float4 a = acc[i];
                a.x *= corr; a.y *= corr; a.z *= corr; a.w *= corr;
#pragma unroll
                for (int jj = 0; jj < 8; jj++) {
                    float4 vv = Vs[c + jj][i];
                    a.x = fmaf(p[jj], vv.x, a.x);
                    a.y = fmaf(p[jj], vv.y, a.y);
                    a.z = fmaf(p[jj], vv.z, a.z);
                    a.w = fmaf(p[jj], vv.w, a.w);
                }
                acc[i] = a;
            }
        }
    }

    float invl = 1.0f / l;
    float4* O4 = (float4*)O;
    size_t obase = ((size_t)(b * SS + qpos) * NH + h) * 16;
#pragma unroll
    for (int i = 0; i < 16; i++) {
        float4 a = acc[i];
        a.x *= invl; a.y *= invl; a.z *= invl; a.w *= invl;
        O4[obase + i] = a;
    }
}

// ============================================================
// launch
// ============================================================
extern "C" void kernel_launch(void* const* d_in, const int* in_sizes, int n_in,
                              void* d_out, int out_size)
{
    const float* x  = (const float*)d_in[0];
    const float* Wq = (const float*)d_in[1];
    const float* Wk = (const float*)d_in[2];
    const float* Wv = (const float*)d_in[3];
    const float* Wo = (const float*)d_in[4];
    float* out = (float*)d_out;

    float *q, *k, *v, *ctx;
    cudaGetSymbolAddress((void**)&q,   g_q);
    cudaGetSymbolAddress((void**)&k,   g_k);
    cudaGetSymbolAddress((void**)&v,   g_v);
    cudaGetSymbolAddress((void**)&ctx, g_ctx);

    const int M = BB * SS;  // 8192

    // QKV projections (tf32 tensor cores)
    gemm_tf32<<<dim3((NH * DK) / 128, M / 128), 256>>>(x, Wq, q, M, NH * DK, DD);
    gemm_tf32<<<dim3((NKV * DK) / 128, M / 128), 256>>>(x, Wk, k, M, NKV * DK, DD);
    gemm_tf32<<<dim3((NKV * DK) / 128, M / 128), 256>>>(x, Wv, v, M, NKV * DK, DD);

    // RoPE on q and k
    {
        int nq = M * NH * 32;
        rope_kernel<<<(nq + 255) / 256, 256>>>(q, nq, NH);
        int nk = M * NKV * 32;
        rope_kernel<<<(nk + 255) / 256, 256>>>(k, nk, NKV);
    }

    // causal GQA attention
    flash_kernel<<<dim3(SS / 128, NH, BB), 128>>>(q, k, v, ctx);

    // output projection
    gemm_tf32<<<dim3(DD / 128, M / 128), 256>>>(ctx, Wo, out, M, DD, DD);
}

// round 3
// speedup vs baseline: 3.3996x; 2.3599x over previous
#include <cuda_runtime.h>
#include <cuda_bf16.h>
#include <math.h>
#include <stdint.h>

// Problem constants
#define BB   4
#define SS   2048
#define DD   1024
#define NH   16
#define NKV  4
#define DK   64
#define NG   (NH / NKV)   // 4

// -------- scratch (no allocations allowed) --------
__device__ float g_q[BB * SS * NH * DK];
__device__ float g_k[BB * SS * NKV * DK];
__device__ float g_v[BB * SS * NKV * DK];
__device__ float g_ctx[BB * SS * DD];

__device__ __forceinline__ float tf32r(float x) {
    uint32_t u;
    asm("cvt.rna.tf32.f32 %0, %1;" : "=r"(u) : "f"(x));
    return __uint_as_float(u);
}
__device__ __forceinline__ uint32_t tf32u(float x) {
    uint32_t u;
    asm("cvt.rna.tf32.f32 %0, %1;" : "=r"(u) : "f"(x));
    return u;
}
__device__ __forceinline__ void mma_tf32(float c[4],
    uint32_t a0, uint32_t a1, uint32_t a2, uint32_t a3,
    uint32_t b0, uint32_t b1)
{
    asm volatile(
        "mma.sync.aligned.m16n8k8.row.col.f32.tf32.tf32.f32 "
        "{%0,%1,%2,%3}, {%4,%5,%6,%7}, {%8,%9}, {%0,%1,%2,%3};\n"
        : "+f"(c[0]), "+f"(c[1]), "+f"(c[2]), "+f"(c[3])
        : "r"(a0), "r"(a1), "r"(a2), "r"(a3), "r"(b0), "r"(b1));
}

// ============================================================
// TF32 tensor-core GEMM: C[M,N] = A[M,K] @ B[K,N]
// 128x128x32 tiles, 256 threads, warp tile 64x32 (m16n8k8)
// ============================================================
#define AS_STRIDE 36
#define BS_STRIDE 136

__global__ __launch_bounds__(256) void gemm_tf32(
    const float* __restrict__ A, const float* __restrict__ B,
    float* __restrict__ C, int M, int N, int K)
{
    __shared__ __align__(16) float As[128 * AS_STRIDE];
    __shared__ __align__(16) float Bs[32 * BS_STRIDE];

    const int tid  = threadIdx.x;
    const int warp = tid >> 5;
    const int lane = tid & 31;
    const int lr   = lane >> 2;
    const int lc   = lane & 3;
    const int wrow = (warp & 1) * 64;
    const int wcol = (warp >> 1) * 32;
    const long rowBase = (long)blockIdx.y * 128;
    const long colBase = (long)blockIdx.x * 128;

    const int arow = tid >> 1;
    const int af4  = (tid & 1) * 4;
    const int brow = tid >> 3;
    const int bf4  = tid & 7;

    const float* Aptr = A + (rowBase + arow) * (long)K + af4 * 4;
    const float* Bptr = B + (long)brow * N + colBase + bf4 * 4;

    float acc[4][4][4];
#pragma unroll
    for (int i = 0; i < 4; i++)
#pragma unroll
        for (int j = 0; j < 4; j++)
#pragma unroll
            for (int r = 0; r < 4; r++) acc[i][j][r] = 0.0f;

    float4 ra[4], rb[4];
#pragma unroll
    for (int i = 0; i < 4; i++) ra[i] = *(const float4*)(Aptr + i * 4);
#pragma unroll
    for (int i = 0; i < 4; i++) rb[i] = *(const float4*)(Bptr + i * 32);

#pragma unroll
    for (int i = 0; i < 4; i++) {
        float4 t = ra[i];
        t.x = tf32r(t.x); t.y = tf32r(t.y); t.z = tf32r(t.z); t.w = tf32r(t.w);
        *(float4*)&As[arow * AS_STRIDE + af4 * 4 + i * 4] = t;
        float4 u = rb[i];
        u.x = tf32r(u.x); u.y = tf32r(u.y); u.z = tf32r(u.z); u.w = tf32r(u.w);
        *(float4*)&Bs[brow * BS_STRIDE + bf4 * 4 + i * 32] = u;
    }
    __syncthreads();

    for (int k0 = 32;; k0 += 32) {
        const bool more = (k0 < K);
        if (more) {
#pragma unroll
            for (int i = 0; i < 4; i++) ra[i] = *(const float4*)(Aptr + k0 + i * 4);
#pragma unroll
            for (int i = 0; i < 4; i++) rb[i] = *(const float4*)(Bptr + (long)k0 * N + i * 32);
        }
        const uint32_t* Au = (const uint32_t*)As;
        const uint32_t* Bu = (const uint32_t*)Bs;
#pragma unroll
        for (int ks = 0; ks < 4; ks++) {
            const int kk = ks * 8;
            uint32_t a[4][4], b[4][2];
#pragma unroll
            for (int ma = 0; ma < 4; ma++) {
                int r = wrow + ma * 16 + lr;
                a[ma][0] = Au[r * AS_STRIDE + kk + lc];
                a[ma][1] = Au[(r + 8) * AS_STRIDE + kk + lc];
                a[ma][2] = Au[r * AS_STRIDE + kk + lc + 4];
                a[ma][3] = Au[(r + 8) * AS_STRIDE + kk + lc + 4];
            }
#pragma unroll
            for (int na = 0; na < 4; na++) {
                int c = wcol + na * 8 + lr;
                b[na][0] = Bu[(kk + lc) * BS_STRIDE + c];
                b[na][1] = Bu[(kk + lc + 4) * BS_STRIDE + c];
            }
#pragma unroll
            for (int ma = 0; ma < 4; ma++)
#pragma unroll
                for (int na = 0; na < 4; na++)
                    mma_tf32(acc[ma][na], a[ma][0], a[ma][1], a[ma][2], a[ma][3],
                             b[na][0], b[na][1]);
        }
        if (!more) break;
        __syncthreads();
#pragma unroll
        for (int i = 0; i < 4; i++) {
            float4 t = ra[i];
            t.x = tf32r(t.x); t.y = tf32r(t.y); t.z = tf32r(t.z); t.w = tf32r(t.w);
            *(float4*)&As[arow * AS_STRIDE + af4 * 4 + i * 4] = t;
            float4 u = rb[i];
            u.x = tf32r(u.x); u.y = tf32r(u.y); u.z = tf32r(u.z); u.w = tf32r(u.w);
            *(float4*)&Bs[brow * BS_STRIDE + bf4 * 4 + i * 32] = u;
        }
        __syncthreads();
    }

#pragma unroll
    for (int ma = 0; ma < 4; ma++) {
#pragma unroll
        for (int na = 0; na < 4; na++) {
            long r = rowBase + wrow + ma * 16 + lr;
            long c = colBase + wcol + na * 8 + 2 * lc;
            *(float2*)(C + r * N + c)       = make_float2(acc[ma][na][0], acc[ma][na][1]);
            *(float2*)(C + (r + 8) * N + c) = make_float2(acc[ma][na][2], acc[ma][na][3]);
        }
    }
}

// ============================================================
// RoPE, in place. t layout: [B*S, H, 64].
// ============================================================
__global__ void rope_kernel(float* __restrict__ t, int total, int H)
{
    int idx = blockIdx.x * blockDim.x + threadIdx.x;
    if (idx >= total) return;
    int i  = idx & 31;
    int rh = idx >> 5;
    int s  = (rh / H) % SS;

    float inv_freq = powf(10000.0f, -(float)i / 32.0f);
    float ang = (float)s * inv_freq;
    float c, sn;
    sincosf(ang, &sn, &c);

    float* p = t + (size_t)rh * 64 + i;
    float a  = p[0];
    float b  = p[32];
    p[0]  = a * c - b * sn;
    p[32] = b * c + a * sn;
}

// ============================================================
// Tensor-core causal GQA flash attention (TF32 mma).
// grid: (S/64, NH, B); 128 threads (4 warps x 16 query rows).
// ============================================================
#define KSTR 68
#define VSTR 72
#define PSTR 68
#define FLASH_SMEM ((64 * KSTR + 64 * VSTR + 64 * PSTR) * 4)

__global__ __launch_bounds__(128) void flash_mma(
    const float* __restrict__ Q, const float* __restrict__ K,
    const float* __restrict__ V, float* __restrict__ O)
{
    extern __shared__ __align__(16) float smem[];
    float* sK = smem;                 // [64][KSTR]
    float* sV = sK + 64 * KSTR;       // [64][VSTR]
    float* sP = sV + 64 * VSTR;       // Q staging, then per-warp P [16][PSTR]

    const int tid  = threadIdx.x;
    const int warp = tid >> 5;
    const int lane = tid & 31;
    const int lr   = lane >> 2;
    const int lc   = lane & 3;
    const int qtile = gridDim.x - 1 - blockIdx.x;   // longest first
    const int qb   = qtile * 64;
    const int h    = blockIdx.y;
    const int b    = blockIdx.z;
    const int kvh  = h >> 2;

    // stage Q (scaled by 1/8, tf32-rounded)
    for (int i = tid; i < 64 * 16; i += 128) {
        int r = i >> 4, c4 = (i & 15) << 2;
        float4 t = *(const float4*)(Q + (((size_t)(b * SS + qb + r) * NH + h) << 6) + c4);
        float4 o;
        o.x = tf32r(t.x * 0.125f); o.y = tf32r(t.y * 0.125f);
        o.z = tf32r(t.z * 0.125f); o.w = tf32r(t.w * 0.125f);
        *(float4*)&sP[r * PSTR + c4] = o;
    }
    __syncthreads();

    // extract Q a-fragments (warp reads only its own 16-row slice)
    uint32_t qf[8][4];
    {
        const uint32_t* pq = (const uint32_t*)(sP + warp * 16 * PSTR);
#pragma unroll
        for (int kc = 0; kc < 8; kc++) {
            qf[kc][0] = pq[lr * PSTR + kc * 8 + lc];
            qf[kc][1] = pq[(lr + 8) * PSTR + kc * 8 + lc];
            qf[kc][2] = pq[lr * PSTR + kc * 8 + lc + 4];
            qf[kc][3] = pq[(lr + 8) * PSTR + kc * 8 + lc + 4];
        }
    }

    float acc[8][4];
#pragma unroll
    for (int na = 0; na < 8; na++)
#pragma unroll
        for (int r = 0; r < 4; r++) acc[na][r] = 0.0f;
    float m_lo = -1e30f, m_hi = -1e30f, l_lo = 0.0f, l_hi = 0.0f;

    float* pw = sP + warp * 16 * PSTR;

    for (int kt = 0; kt <= qtile; kt++) {
        __syncthreads();
        for (int i = tid; i < 64 * 16; i += 128) {
            int r = i >> 4, c4 = (i & 15) << 2;
            size_t src = (((size_t)(b * SS + kt * 64 + r) * NKV + kvh) << 6) + c4;
            float4 tk = *(const float4*)(K + src);
            float4 tv = *(const float4*)(V + src);
            float4 ok, ov;
            ok.x = tf32r(tk.x); ok.y = tf32r(tk.y); ok.z = tf32r(tk.z); ok.w = tf32r(tk.w);
            ov.x = tf32r(tv.x); ov.y = tf32r(tv.y); ov.z = tf32r(tv.z); ov.w = tf32r(tv.w);
            *(float4*)&sK[r * KSTR + c4] = ok;
            *(float4*)&sV[r * VSTR + c4] = ov;
        }
        __syncthreads();

        // S = Q @ K^T  (scores, pre-scaled)
        float sc[8][4];
#pragma unroll
        for (int na = 0; na < 8; na++) {
            sc[na][0] = sc[na][1] = sc[na][2] = sc[na][3] = 0.0f;
        }
        const uint32_t* Ku = (const uint32_t*)sK;
#pragma unroll
        for (int na = 0; na < 8; na++) {
#pragma unroll
            for (int kc = 0; kc < 8; kc++) {
                uint32_t b0 = Ku[(na * 8 + lr) * KSTR + kc * 8 + lc];
                uint32_t b1 = Ku[(na * 8 + lr) * KSTR + kc * 8 + lc + 4];
                mma_tf32(sc[na], qf[kc][0], qf[kc][1], qf[kc][2], qf[kc][3], b0, b1);
            }
        }

        if (kt == qtile) {  // diagonal causal mask
            int r0 = warp * 16 + lr;
            int r1 = r0 + 8;
#pragma unroll
            for (int na = 0; na < 8; na++) {
                int col = na * 8 + 2 * lc;
                if (col     > r0) sc[na][0] = -1e30f;
                if (col + 1 > r0) sc[na][1] = -1e30f;
                if (col     > r1) sc[na][2] = -1e30f;
                if (col + 1 > r1) sc[na][3] = -1e30f;
            }
        }

        // online softmax
        float rm_lo = -1e30f, rm_hi = -1e30f;
#pragma unroll
        for (int na = 0; na < 8; na++) {
            rm_lo = fmaxf(rm_lo, fmaxf(sc[na][0], sc[na][1]));
            rm_hi = fmaxf(rm_hi, fmaxf(sc[na][2], sc[na][3]));
        }
        rm_lo = fmaxf(rm_lo, __shfl_xor_sync(0xffffffff, rm_lo, 1));
        rm_lo = fmaxf(rm_lo, __shfl_xor_sync(0xffffffff, rm_lo, 2));
        rm_hi = fmaxf(rm_hi, __shfl_xor_sync(0xffffffff, rm_hi, 1));
        rm_hi = fmaxf(rm_hi, __shfl_xor_sync(0xffffffff, rm_hi, 2));

        float mn_lo = fmaxf(m_lo, rm_lo);
        float mn_hi = fmaxf(m_hi, rm_hi);
        float corr_lo = __expf(m_lo - mn_lo);
        float corr_hi = __expf(m_hi - mn_hi);
        m_lo = mn_lo; m_hi = mn_hi;

        float ps_lo = 0.0f, ps_hi = 0.0f;
#pragma unroll
        for (int na = 0; na < 8; na++) {
            float p0 = __expf(sc[na][0] - m_lo);
            float p1 = __expf(sc[na][1] - m_lo);
            float p2 = __expf(sc[na][2] - m_hi);
            float p3 = __expf(sc[na][3] - m_hi);
            ps_lo += p0 + p1;
            ps_hi += p2 + p3;
            pw[lr * PSTR + na * 8 + 2 * lc]           = tf32r(p0);
            pw[lr * PSTR + na * 8 + 2 * lc + 1]       = tf32r(p1);
            pw[(lr + 8) * PSTR + na * 8 + 2 * lc]     = tf32r(p2);
            pw[(lr + 8) * PSTR + na * 8 + 2 * lc + 1] = tf32r(p3);
            acc[na][0] *= corr_lo; acc[na][1] *= corr_lo;
            acc[na][2] *= corr_hi; acc[na][3] *= corr_hi;
        }
        ps_lo += __shfl_xor_sync(0xffffffff, ps_lo, 1);
        ps_lo += __shfl_xor_sync(0xffffffff, ps_lo, 2);
        ps_hi += __shfl_xor_sync(0xffffffff, ps_hi, 1);
        ps_hi += __shfl_xor_sync(0xffffffff, ps_hi, 2);
        l_lo = l_lo * corr_lo + ps_lo;
        l_hi = l_hi * corr_hi + ps_hi;

        __syncwarp();

        // O += P @ V
        const uint32_t* Pu = (const uint32_t*)pw;
        const uint32_t* Vu = (const uint32_t*)sV;
#pragma unroll
        for (int kc = 0; kc < 8; kc++) {
            uint32_t a0 = Pu[lr * PSTR + kc * 8 + lc];
            uint32_t a1 = Pu[(lr + 8) * PSTR + kc * 8 + lc];
            uint32_t a2 = Pu[lr * PSTR + kc * 8 + lc + 4];
            uint32_t a3 = Pu[(lr + 8) * PSTR + kc * 8 + lc + 4];
#pragma unroll
            for (int na = 0; na < 8; na++) {
                uint32_t b0 = Vu[(kc * 8 + lc) * VSTR + na * 8 + lr];
                uint32_t b1 = Vu[(kc * 8 + lc + 4) * VSTR + na * 8 + lr];
                mma_tf32(acc[na], a0, a1, a2, a3, b0, b1);
            }
        }
    }

    float inv_lo = 1.0f / l_lo;
    float inv_hi = 1.0f / l_hi;
    size_t r0 = (size_t)(b * SS + qb + warp * 16 + lr);
    size_t r1 = r0 + 8;
#pragma unroll
    for (int na = 0; na < 8; na++) {
        int col = na * 8 + 2 * lc;
        *(float2*)(O + ((r0 * NH + h) << 6) + col) =
            make_float2(acc[na][0] * inv_lo, acc[na][1] * inv_lo);
        *(float2*)(O + ((r1 * NH + h) << 6) + col) =
            make_float2(acc[na][2] * inv_hi, acc[na][3] * inv_hi);
    }
}

// ============================================================
// launch
// ============================================================
extern "C" void kernel_launch(void* const* d_in, const int* in_sizes, int n_in,
                              void* d_out, int out_size)
{
    const float* x  = (const float*)d_in[0];
    const float* Wq = (const float*)d_in[1];
    const float* Wk = (const float*)d_in[2];
    const float* Wv = (const float*)d_in[3];
    const float* Wo = (const float*)d_in[4];
    float* out = (float*)d_out;

    float *q, *k, *v, *ctx;
    cudaGetSymbolAddress((void**)&q,   g_q);
    cudaGetSymbolAddress((void**)&k,   g_k);
    cudaGetSymbolAddress((void**)&v,   g_v);
    cudaGetSymbolAddress((void**)&ctx, g_ctx);

    const int M = BB * SS;  // 8192

    gemm_tf32<<<dim3((NH * DK) / 128, M / 128), 256>>>(x, Wq, q, M, NH * DK, DD);
    gemm_tf32<<<dim3((NKV * DK) / 128, M / 128), 256>>>(x, Wk, k, M, NKV * DK, DD);
    gemm_tf32<<<dim3((NKV * DK) / 128, M / 128), 256>>>(x, Wv, v, M, NKV * DK, DD);

    {
        int nq = M * NH * 32;
        rope_kernel<<<(nq + 255) / 256, 256>>>(q, nq, NH);
        int nk = M * NKV * 32;
        rope_kernel<<<(nk + 255) / 256, 256>>>(k, nk, NKV);
    }

    cudaFuncSetAttribute(flash_mma, cudaFuncAttributeMaxDynamicSharedMemorySize, FLASH_SMEM);
    flash_mma<<<dim3(SS / 64, NH, BB), 128, FLASH_SMEM>>>(q, k, v, ctx);

    gemm_tf32<<<dim3(DD / 128, M / 128), 256>>>(ctx, Wo, out, M, DD, DD);
}

// round 4
// speedup vs baseline: 4.3946x; 1.2927x over previous
#include <cuda_runtime.h>
#include <cuda_fp16.h>
#include <math.h>
#include <stdint.h>

// Problem constants
#define BB   4
#define SS   2048
#define DD   1024
#define NH   16
#define NKV  4
#define DK   64
#define NG   (NH / NKV)

// -------- scratch --------
__device__ float g_q[BB * SS * NH * DK];
__device__ float g_k[BB * SS * NKV * DK];
__device__ float g_v[BB * SS * NKV * DK];
__device__ float g_ctx[BB * SS * DD];

__device__ __forceinline__ uint32_t h2(float a, float b) {
    __half2 h = __floats2half2_rn(a, b);
    return *(uint32_t*)&h;
}
__device__ __forceinline__ void mma_f16(float c[4],
    uint32_t a0, uint32_t a1, uint32_t a2, uint32_t a3,
    uint32_t b0, uint32_t b1)
{
    asm volatile(
        "mma.sync.aligned.m16n8k16.row.col.f32.f16.f16.f32 "
        "{%0,%1,%2,%3}, {%4,%5,%6,%7}, {%8,%9}, {%0,%1,%2,%3};\n"
        : "+f"(c[0]), "+f"(c[1]), "+f"(c[2]), "+f"(c[3])
        : "r"(a0), "r"(a1), "r"(a2), "r"(a3), "r"(b0), "r"(b1));
}

// ============================================================
// FP16 tensor-core GEMM: C[M,N] = A[M,K] @ B[K,N]
// 128x128x32 tiles, 256 threads, warp tile 64x32 (m16n8k16)
// smem in half2 words: A stride 20 (16 data +4), B stride 136.
// ============================================================
#define GA_STR 20
#define GB_STR 136

__global__ __launch_bounds__(256) void gemm_f16(
    const float* __restrict__ A, const float* __restrict__ B,
    float* __restrict__ C, int M, int N, int K)
{
    __shared__ __align__(16) uint32_t As2[128 * GA_STR];
    __shared__ __align__(16) uint32_t Bs2[16 * GB_STR];

    const int tid  = threadIdx.x;
    const int warp = tid >> 5;
    const int lane = tid & 31;
    const int lr   = lane >> 2;
    const int lc   = lane & 3;
    const int wrow = (warp & 1) * 64;
    const int wcol = (warp >> 1) * 32;
    const long rowBase = (long)blockIdx.y * 128;
    const long colBase = (long)blockIdx.x * 128;

    // A loader: 2 threads per row, 16 floats each
    const int arow = tid >> 1;
    const int af   = (tid & 1) * 16;
    // B loader: thread handles k rows 2bk,2bk+1, 8 cols
    const int bk   = tid >> 4;
    const int bc   = (tid & 15) * 8;

    const float* Aptr  = A + (rowBase + arow) * (long)K + af;
    const float* Bptr0 = B + (long)(2 * bk) * N + colBase + bc;
    const float* Bptr1 = Bptr0 + N;

    float acc[4][4][4];
#pragma unroll
    for (int i = 0; i < 4; i++)
#pragma unroll
        for (int j = 0; j < 4; j++)
#pragma unroll
            for (int r = 0; r < 4; r++) acc[i][j][r] = 0.0f;

    float4 ra[4], rb0[2], rb1[2];

#pragma unroll
    for (int i = 0; i < 4; i++) ra[i] = *(const float4*)(Aptr + i * 4);
    rb0[0] = *(const float4*)(Bptr0);     rb0[1] = *(const float4*)(Bptr0 + 4);
    rb1[0] = *(const float4*)(Bptr1);     rb1[1] = *(const float4*)(Bptr1 + 4);

    {
        uint32_t wA[8];
#pragma unroll
        for (int i = 0; i < 4; i++) {
            wA[2*i]   = h2(ra[i].x, ra[i].y);
            wA[2*i+1] = h2(ra[i].z, ra[i].w);
        }
        int wb = arow * GA_STR + (af >> 1);
        *(uint4*)&As2[wb]     = make_uint4(wA[0], wA[1], wA[2], wA[3]);
        *(uint4*)&As2[wb + 4] = make_uint4(wA[4], wA[5], wA[6], wA[7]);
        uint32_t wB[8];
#pragma unroll
        for (int i = 0; i < 2; i++) {
            const float* p0 = (const float*)&rb0[i];
            const float* p1 = (const float*)&rb1[i];
#pragma unroll
            for (int f = 0; f < 4; f++) wB[i*4+f] = h2(p0[f], p1[f]);
        }
        int wbb = bk * GB_STR + bc;
        *(uint4*)&Bs2[wbb]     = make_uint4(wB[0], wB[1], wB[2], wB[3]);
        *(uint4*)&Bs2[wbb + 4] = make_uint4(wB[4], wB[5], wB[6], wB[7]);
    }
    __syncthreads();

    for (int k0 = 32;; k0 += 32) {
        const bool more = (k0 < K);
        if (more) {
#pragma unroll
            for (int i = 0; i < 4; i++) ra[i] = *(const float4*)(Aptr + k0 + i * 4);
            rb0[0] = *(const float4*)(Bptr0 + (long)k0 * N);
            rb0[1] = *(const float4*)(Bptr0 + (long)k0 * N + 4);
            rb1[0] = *(const float4*)(Bptr1 + (long)k0 * N);
            rb1[1] = *(const float4*)(Bptr1 + (long)k0 * N + 4);
        }

#pragma unroll
        for (int kc = 0; kc < 2; kc++) {
            const int base = kc * 8;
            uint32_t a[4][4], b[4][2];
#pragma unroll
            for (int ma = 0; ma < 4; ma++) {
                int r = wrow + ma * 16 + lr;
                a[ma][0] = As2[r * GA_STR + base + lc];
                a[ma][1] = As2[(r + 8) * GA_STR + base + lc];
                a[ma][2] = As2[r * GA_STR + base + lc + 4];
                a[ma][3] = As2[(r + 8) * GA_STR + base + lc + 4];
            }
#pragma unroll
            for (int na = 0; na < 4; na++) {
                int c = wcol + na * 8 + lr;
                b[na][0] = Bs2[(base + lc) * GB_STR + c];
                b[na][1] = Bs2[(base + lc + 4) * GB_STR + c];
            }
#pragma unroll
            for (int ma = 0; ma < 4; ma++)
#pragma unroll
                for (int na = 0; na < 4; na++)
                    mma_f16(acc[ma][na], a[ma][0], a[ma][1], a[ma][2], a[ma][3],
                            b[na][0], b[na][1]);
        }

        if (!more) break;
        __syncthreads();
        {
            uint32_t wA[8];
#pragma unroll
            for (int i = 0; i < 4; i++) {
                wA[2*i]   = h2(ra[i].x, ra[i].y);
                wA[2*i+1] = h2(ra[i].z, ra[i].w);
            }
            int wb = arow * GA_STR + (af >> 1);
            *(uint4*)&As2[wb]     = make_uint4(wA[0], wA[1], wA[2], wA[3]);
            *(uint4*)&As2[wb + 4] = make_uint4(wA[4], wA[5], wA[6], wA[7]);
            uint32_t wB[8];
#pragma unroll
            for (int i = 0; i < 2; i++) {
                const float* p0 = (const float*)&rb0[i];
                const float* p1 = (const float*)&rb1[i];
#pragma unroll
                for (int f = 0; f < 4; f++) wB[i*4+f] = h2(p0[f], p1[f]);
            }
            int wbb = bk * GB_STR + bc;
            *(uint4*)&Bs2[wbb]     = make_uint4(wB[0], wB[1], wB[2], wB[3]);
            *(uint4*)&Bs2[wbb + 4] = make_uint4(wB[4], wB[5], wB[6], wB[7]);
        }
        __syncthreads();
    }

#pragma unroll
    for (int ma = 0; ma < 4; ma++) {
#pragma unroll
        for (int na = 0; na < 4; na++) {
            long r = rowBase + wrow + ma * 16 + lr;
            long c = colBase + wcol + na * 8 + 2 * lc;
            *(float2*)(C + r * N + c)       = make_float2(acc[ma][na][0], acc[ma][na][1]);
            *(float2*)(C + (r + 8) * N + c) = make_float2(acc[ma][na][2], acc[ma][na][3]);
        }
    }
}

// ============================================================
// RoPE, in place. t layout: [B*S, H, 64].
// ============================================================
__global__ void rope_kernel(float* __restrict__ t, int total, int H)
{
    int idx = blockIdx.x * blockDim.x + threadIdx.x;
    if (idx >= total) return;
    int i  = idx & 31;
    int rh = idx >> 5;
    int s  = (rh / H) % SS;

    float inv_freq = powf(10000.0f, -(float)i / 32.0f);
    float ang = (float)s * inv_freq;
    float c, sn;
    sincosf(ang, &sn, &c);

    float* p = t + (size_t)rh * 64 + i;
    float a  = p[0];
    float b  = p[32];
    p[0]  = a * c - b * sn;
    p[32] = b * c + a * sn;
}

// ============================================================
// FP16 tensor-core causal GQA flash attention.
// grid: (S/64, NH, B); 128 threads (4 warps x 16 query rows).
// smem word strides: Q/K 36, V 72, P 36.
// ============================================================
#define FQ_STR 36
#define FV_STR 72
#define FP_STR 36

__global__ __launch_bounds__(128) void flash_f16(
    const float* __restrict__ Q, const float* __restrict__ K,
    const float* __restrict__ V, float* __restrict__ O)
{
    __shared__ __align__(16) uint32_t sQ[64 * FQ_STR];
    __shared__ __align__(16) uint32_t sK[64 * FQ_STR];
    __shared__ __align__(16) uint32_t sV[32 * FV_STR];
    __shared__ __align__(16) uint32_t sP[4 * 16 * FP_STR];

    const int tid  = threadIdx.x;
    const int warp = tid >> 5;
    const int lane = tid & 31;
    const int lr   = lane >> 2;
    const int lc   = lane & 3;
    const int qtile = gridDim.x - 1 - blockIdx.x;
    const int qb   = qtile * 64;
    const int h    = blockIdx.y;
    const int b    = blockIdx.z;
    const int kvh  = h >> 2;

    // stage Q (scaled 1/8) as half2 words
    for (int i = tid; i < 64 * 16; i += 128) {
        int r = i >> 4, c4 = (i & 15) << 2;
        float4 t = *(const float4*)(Q + (((size_t)(b * SS + qb + r) * NH + h) << 6) + c4);
        int wb = r * FQ_STR + (c4 >> 1);
        sQ[wb]     = h2(t.x * 0.125f, t.y * 0.125f);
        sQ[wb + 1] = h2(t.z * 0.125f, t.w * 0.125f);
    }
    __syncthreads();

    uint32_t qf[4][4];
    {
        const uint32_t* pq = sQ + warp * 16 * FQ_STR;
#pragma unroll
        for (int kc = 0; kc < 4; kc++) {
            qf[kc][0] = pq[lr * FQ_STR + kc * 8 + lc];
            qf[kc][1] = pq[(lr + 8) * FQ_STR + kc * 8 + lc];
            qf[kc][2] = pq[lr * FQ_STR + kc * 8 + lc + 4];
            qf[kc][3] = pq[(lr + 8) * FQ_STR + kc * 8 + lc + 4];
        }
    }

    float acc[8][4];
#pragma unroll
    for (int na = 0; na < 8; na++)
#pragma unroll
        for (int r = 0; r < 4; r++) acc[na][r] = 0.0f;
    float m_lo = -1e30f, m_hi = -1e30f, l_lo = 0.0f, l_hi = 0.0f;

    uint32_t* pw = sP + warp * 16 * FP_STR;

    for (int kt = 0; kt <= qtile; kt++) {
        __syncthreads();
        // K rows as-is (feature pairs)
        for (int i = tid; i < 64 * 16; i += 128) {
            int r = i >> 4, c4 = (i & 15) << 2;
            size_t src = (((size_t)(b * SS + kt * 64 + r) * NKV + kvh) << 6) + c4;
            float4 t = *(const float4*)(K + src);
            int wb = r * FQ_STR + (c4 >> 1);
            sK[wb]     = h2(t.x, t.y);
            sK[wb + 1] = h2(t.z, t.w);
        }
        // V key-pairs per feature
        for (int i = tid; i < 32 * 16; i += 128) {
            int kp = i >> 4, f4 = (i & 15) << 2;
            size_t s0 = (((size_t)(b * SS + kt * 64 + 2 * kp) * NKV + kvh) << 6) + f4;
            float4 v0 = *(const float4*)(V + s0);
            float4 v1 = *(const float4*)(V + s0 + (NKV << 6));
            *(uint4*)&sV[kp * FV_STR + f4] = make_uint4(
                h2(v0.x, v1.x), h2(v0.y, v1.y), h2(v0.z, v1.z), h2(v0.w, v1.w));
        }
        __syncthreads();

        // S = Q @ K^T
        float sc[8][4];
#pragma unroll
        for (int na = 0; na < 8; na++)
            sc[na][0] = sc[na][1] = sc[na][2] = sc[na][3] = 0.0f;
#pragma unroll
        for (int na = 0; na < 8; na++) {
#pragma unroll
            for (int kc = 0; kc < 4; kc++) {
                uint32_t b0 = sK[(na * 8 + lr) * FQ_STR + kc * 8 + lc];
                uint32_t b1 = sK[(na * 8 + lr) * FQ_STR + kc * 8 + lc + 4];
                mma_f16(sc[na], qf[kc][0], qf[kc][1], qf[kc][2], qf[kc][3], b0, b1);
            }
        }

        if (kt == qtile) {
            int r0 = warp * 16 + lr;
            int r1 = r0 + 8;
#pragma unroll
            for (int na = 0; na < 8; na++) {
                int col = na * 8 + 2 * lc;
                if (col     > r0) sc[na][0] = -1e30f;
                if (col + 1 > r0) sc[na][1] = -1e30f;
                if (col     > r1) sc[na][2] = -1e30f;
                if (col + 1 > r1) sc[na][3] = -1e30f;
            }
        }

        // online softmax
        float rm_lo = -1e30f, rm_hi = -1e30f;
#pragma unroll
        for (int na = 0; na < 8; na++) {
            rm_lo = fmaxf(rm_lo, fmaxf(sc[na][0], sc[na][1]));
            rm_hi = fmaxf(rm_hi, fmaxf(sc[na][2], sc[na][3]));
        }
        rm_lo = fmaxf(rm_lo, __shfl_xor_sync(0xffffffff, rm_lo, 1));
        rm_lo = fmaxf(rm_lo, __shfl_xor_sync(0xffffffff, rm_lo, 2));
        rm_hi = fmaxf(rm_hi, __shfl_xor_sync(0xffffffff, rm_hi, 1));
        rm_hi = fmaxf(rm_hi, __shfl_xor_sync(0xffffffff, rm_hi, 2));

        float mn_lo = fmaxf(m_lo, rm_lo);
        float mn_hi = fmaxf(m_hi, rm_hi);
        float corr_lo = __expf(m_lo - mn_lo);
        float corr_hi = __expf(m_hi - mn_hi);
        m_lo = mn_lo; m_hi = mn_hi;

        float ps_lo = 0.0f, ps_hi = 0.0f;
#pragma unroll
        for (int na = 0; na < 8; na++) {
            float p0 = __expf(sc[na][0] - m_lo);
            float p1 = __expf(sc[na][1] - m_lo);
            float p2 = __expf(sc[na][2] - m_hi);
            float p3 = __expf(sc[na][3] - m_hi);
            ps_lo += p0 + p1;
            ps_hi += p2 + p3;
            pw[lr * FP_STR + na * 4 + lc]       = h2(p0, p1);
            pw[(lr + 8) * FP_STR + na * 4 + lc] = h2(p2, p3);
            acc[na][0] *= corr_lo; acc[na][1] *= corr_lo;
            acc[na][2] *= corr_hi; acc[na][3] *= corr_hi;
        }
        ps_lo += __shfl_xor_sync(0xffffffff, ps_lo, 1);
        ps_lo += __shfl_xor_sync(0xffffffff, ps_lo, 2);
        ps_hi += __shfl_xor_sync(0xffffffff, ps_hi, 1);
        ps_hi += __shfl_xor_sync(0xffffffff, ps_hi, 2);
        l_lo = l_lo * corr_lo + ps_lo;
        l_hi = l_hi * corr_hi + ps_hi;

        __syncwarp();

        // O += P @ V
#pragma unroll
        for (int kc = 0; kc < 4; kc++) {
            uint32_t a0 = pw[lr * FP_STR + kc * 8 + lc];
            uint32_t a1 = pw[(lr + 8) * FP_STR + kc * 8 + lc];
            uint32_t a2 = pw[lr * FP_STR + kc * 8 + lc + 4];
            uint32_t a3 = pw[(lr + 8) * FP_STR + kc * 8 + lc + 4];
#pragma unroll
            for (int na = 0; na < 8; na++) {
                uint32_t b0 = sV[(kc * 8 + lc) * FV_STR + na * 8 + lr];
                uint32_t b1 = sV[(kc * 8 + lc + 4) * FV_STR + na * 8 + lr];
                mma_f16(acc[na], a0, a1, a2, a3, b0, b1);
            }
        }
    }

    float inv_lo = 1.0f / l_lo;
    float inv_hi = 1.0f / l_hi;
    size_t r0 = (size_t)(b * SS + qb + warp * 16 + lr);
    size_t r1 = r0 + 8;
#pragma unroll
    for (int na = 0; na < 8; na++) {
        int col = na * 8 + 2 * lc;
        *(float2*)(O + ((r0 * NH + h) << 6) + col) =
            make_float2(acc[na][0] * inv_lo, acc[na][1] * inv_lo);
        *(float2*)(O + ((r1 * NH + h) << 6) + col) =
            make_float2(acc[na][2] * inv_hi, acc[na][3] * inv_hi);
    }
}

// ============================================================
// launch
// ============================================================
extern "C" void kernel_launch(void* const* d_in, const int* in_sizes, int n_in,
                              void* d_out, int out_size)
{
    const float* x  = (const float*)d_in[0];
    const float* Wq = (const float*)d_in[1];
    const float* Wk = (const float*)d_in[2];
    const float* Wv = (const float*)d_in[3];
    const float* Wo = (const float*)d_in[4];
    float* out = (float*)d_out;

    float *q, *k, *v, *ctx;
    cudaGetSymbolAddress((void**)&q,   g_q);
    cudaGetSymbolAddress((void**)&k,   g_k);
    cudaGetSymbolAddress((void**)&v,   g_v);
    cudaGetSymbolAddress((void**)&ctx, g_ctx);

    const int M = BB * SS;  // 8192

    gemm_f16<<<dim3((NH * DK) / 128, M / 128), 256>>>(x, Wq, q, M, NH * DK, DD);
    gemm_f16<<<dim3((NKV * DK) / 128, M / 128), 256>>>(x, Wk, k, M, NKV * DK, DD);
    gemm_f16<<<dim3((NKV * DK) / 128, M / 128), 256>>>(x, Wv, v, M, NKV * DK, DD);

    {
        int nq = M * NH * 32;
        rope_kernel<<<(nq + 255) / 256, 256>>>(q, nq, NH);
        int nk = M * NKV * 32;
        rope_kernel<<<(nk + 255) / 256, 256>>>(k, nk, NKV);
    }

    flash_f16<<<dim3(SS / 64, NH, BB), 128>>>(q, k, v, ctx);

    gemm_f16<<<dim3(DD / 128, M / 128), 256>>>(ctx, Wo, out, M, DD, DD);
}

// round 5
// speedup vs baseline: 5.0109x; 1.1402x over previous
#include <cuda_runtime.h>
#include <cuda_fp16.h>
#include <math.h>
#include <stdint.h>

#define BB   4
#define SS   2048
#define DD   1024
#define NH   16
#define NKV  4
#define DK   64

// -------- scratch (half-precision intermediates, uint4-aligned) --------
__device__ uint4 g_q[BB * SS * NH * DK / 8];
__device__ uint4 g_k[BB * SS * NKV * DK / 8];
__device__ uint4 g_v[BB * SS * NKV * DK / 8];
__device__ uint4 g_ctx[BB * SS * DD / 8];

__device__ __forceinline__ uint32_t h2(float a, float b) {
    __half2 h = __floats2half2_rn(a, b);
    return *(uint32_t*)&h;
}
__device__ __forceinline__ void mma_f16(float c[4],
    uint32_t a0, uint32_t a1, uint32_t a2, uint32_t a3,
    uint32_t b0, uint32_t b1)
{
    asm volatile(
        "mma.sync.aligned.m16n8k16.row.col.f32.f16.f16.f32 "
        "{%0,%1,%2,%3}, {%4,%5,%6,%7}, {%8,%9}, {%0,%1,%2,%3};\n"
        : "+f"(c[0]), "+f"(c[1]), "+f"(c[2]), "+f"(c[3])
        : "r"(a0), "r"(a1), "r"(a2), "r"(a3), "r"(b0), "r"(b1));
}
__device__ __forceinline__ void ldsm4(uint32_t d[4], uint32_t saddr) {
    asm volatile("ldmatrix.sync.aligned.m8n8.x4.shared.b16 {%0,%1,%2,%3}, [%4];\n"
        : "=r"(d[0]), "=r"(d[1]), "=r"(d[2]), "=r"(d[3]) : "r"(saddr));
}
__device__ __forceinline__ void ldsm4t(uint32_t d[4], uint32_t saddr) {
    asm volatile("ldmatrix.sync.aligned.m8n8.x4.trans.shared.b16 {%0,%1,%2,%3}, [%4];\n"
        : "=r"(d[0]), "=r"(d[1]), "=r"(d[2]), "=r"(d[3]) : "r"(saddr));
}

// ============================================================
// FP16 tensor-core GEMM: C[M,N] = A[M,K] @ B[K,N]
// 128x128x32 tiles, 256 threads, warp tile 64x32 (m16n8k16)
// AH: A is half (plain copy staging); CH: C written as half.
// ============================================================
#define GA_STR 20
#define GB_STR 136

template<bool AH, bool CH>
__global__ __launch_bounds__(256) void gemm_f16k(
    const void* __restrict__ Av, const float* __restrict__ B,
    void* __restrict__ Cv, int M, int N, int K)
{
    __shared__ __align__(16) uint32_t As2[128 * GA_STR];
    __shared__ __align__(16) uint32_t Bs2[16 * GB_STR];

    const int tid  = threadIdx.x;
    const int warp = tid >> 5;
    const int lane = tid & 31;
    const int lr   = lane >> 2;
    const int lc   = lane & 3;
    const int wrow = (warp & 1) * 64;
    const int wcol = (warp >> 1) * 32;
    const long rowBase = (long)blockIdx.y * 128;
    const long colBase = (long)blockIdx.x * 128;

    const int arow = tid >> 1;
    const int ahalf = tid & 1;          // which half of the 32-k row
    const int bk   = tid >> 4;
    const int bc   = (tid & 15) * 8;

    const float* Aptr  = AH ? nullptr : (const float*)Av + (rowBase + arow) * (long)K + ahalf * 16;
    const uint4* Aptr4 = AH ? (const uint4*)Av + (rowBase + arow) * (long)(K / 8) + ahalf * 2 : nullptr;
    const float* Bptr0 = B + (long)(2 * bk) * N + colBase + bc;
    const float* Bptr1 = Bptr0 + N;

    float acc[4][4][4];
#pragma unroll
    for (int i = 0; i < 4; i++)
#pragma unroll
        for (int j = 0; j < 4; j++)
#pragma unroll
            for (int r = 0; r < 4; r++) acc[i][j][r] = 0.0f;

    float4 ra[4];
    uint4  ua[2];
    float4 rb0[2], rb1[2];

    // ---- prologue load k0=0 ----
    if (AH) { ua[0] = Aptr4[0]; ua[1] = Aptr4[1]; }
    else {
#pragma unroll
        for (int i = 0; i < 4; i++) ra[i] = *(const float4*)(Aptr + i * 4);
    }
    rb0[0] = *(const float4*)(Bptr0);     rb0[1] = *(const float4*)(Bptr0 + 4);
    rb1[0] = *(const float4*)(Bptr1);     rb1[1] = *(const float4*)(Bptr1 + 4);

    {
        int wb = arow * GA_STR + ahalf * 8;
        if (AH) {
            *(uint4*)&As2[wb]     = ua[0];
            *(uint4*)&As2[wb + 4] = ua[1];
        } else {
            uint32_t wA[8];
#pragma unroll
            for (int i = 0; i < 4; i++) {
                wA[2*i]   = h2(ra[i].x, ra[i].y);
                wA[2*i+1] = h2(ra[i].z, ra[i].w);
            }
            *(uint4*)&As2[wb]     = make_uint4(wA[0], wA[1], wA[2], wA[3]);
            *(uint4*)&As2[wb + 4] = make_uint4(wA[4], wA[5], wA[6], wA[7]);
        }
        uint32_t wB[8];
#pragma unroll
        for (int i = 0; i < 2; i++) {
            const float* p0 = (const float*)&rb0[i];
            const float* p1 = (const float*)&rb1[i];
#pragma unroll
            for (int f = 0; f < 4; f++) wB[i*4+f] = h2(p0[f], p1[f]);
        }
        int wbb = bk * GB_STR + bc;
        *(uint4*)&Bs2[wbb]     = make_uint4(wB[0], wB[1], wB[2], wB[3]);
        *(uint4*)&Bs2[wbb + 4] = make_uint4(wB[4], wB[5], wB[6], wB[7]);
    }
    __syncthreads();

    for (int k0 = 32;; k0 += 32) {
        const bool more = (k0 < K);
        if (more) {
            if (AH) { ua[0] = Aptr4[k0 / 8]; ua[1] = Aptr4[k0 / 8 + 1]; }
            else {
#pragma unroll
                for (int i = 0; i < 4; i++) ra[i] = *(const float4*)(Aptr + k0 + i * 4);
            }
            rb0[0] = *(const float4*)(Bptr0 + (long)k0 * N);
            rb0[1] = *(const float4*)(Bptr0 + (long)k0 * N + 4);
            rb1[0] = *(const float4*)(Bptr1 + (long)k0 * N);
            rb1[1] = *(const float4*)(Bptr1 + (long)k0 * N + 4);
        }

#pragma unroll
        for (int kc = 0; kc < 2; kc++) {
            const int base = kc * 8;
            uint32_t a[4][4], b[4][2];
#pragma unroll
            for (int ma = 0; ma < 4; ma++) {
                int r = wrow + ma * 16 + lr;
                a[ma][0] = As2[r * GA_STR + base + lc];
                a[ma][1] = As2[(r + 8) * GA_STR + base + lc];
                a[ma][2] = As2[r * GA_STR + base + lc + 4];
                a[ma][3] = As2[(r + 8) * GA_STR + base + lc + 4];
            }
#pragma unroll
            for (int na = 0; na < 4; na++) {
                int c = wcol + na * 8 + lr;
                b[na][0] = Bs2[(base + lc) * GB_STR + c];
                b[na][1] = Bs2[(base + lc + 4) * GB_STR + c];
            }
#pragma unroll
            for (int ma = 0; ma < 4; ma++)
#pragma unroll
                for (int na = 0; na < 4; na++)
                    mma_f16(acc[ma][na], a[ma][0], a[ma][1], a[ma][2], a[ma][3],
                            b[na][0], b[na][1]);
        }

        if (!more) break;
        __syncthreads();
        {
            int wb = arow * GA_STR + ahalf * 8;
            if (AH) {
                *(uint4*)&As2[wb]     = ua[0];
                *(uint4*)&As2[wb + 4] = ua[1];
            } else {
                uint32_t wA[8];
#pragma unroll
                for (int i = 0; i < 4; i++) {
                    wA[2*i]   = h2(ra[i].x, ra[i].y);
                    wA[2*i+1] = h2(ra[i].z, ra[i].w);
                }
                *(uint4*)&As2[wb]     = make_uint4(wA[0], wA[1], wA[2], wA[3]);
                *(uint4*)&As2[wb + 4] = make_uint4(wA[4], wA[5], wA[6], wA[7]);
            }
            uint32_t wB[8];
#pragma unroll
            for (int i = 0; i < 2; i++) {
                const float* p0 = (const float*)&rb0[i];
                const float* p1 = (const float*)&rb1[i];
#pragma unroll
                for (int f = 0; f < 4; f++) wB[i*4+f] = h2(p0[f], p1[f]);
            }
            int wbb = bk * GB_STR + bc;
            *(uint4*)&Bs2[wbb]     = make_uint4(wB[0], wB[1], wB[2], wB[3]);
            *(uint4*)&Bs2[wbb + 4] = make_uint4(wB[4], wB[5], wB[6], wB[7]);
        }
        __syncthreads();
    }

#pragma unroll
    for (int ma = 0; ma < 4; ma++) {
#pragma unroll
        for (int na = 0; na < 4; na++) {
            long r = rowBase + wrow + ma * 16 + lr;
            long c = colBase + wcol + na * 8 + 2 * lc;
            if (CH) {
                uint32_t* Ch = (uint32_t*)Cv;
                Ch[(r * N + c) >> 1]       = h2(acc[ma][na][0], acc[ma][na][1]);
                Ch[((r + 8) * N + c) >> 1] = h2(acc[ma][na][2], acc[ma][na][3]);
            } else {
                float* Cf = (float*)Cv;
                *(float2*)(Cf + r * N + c)       = make_float2(acc[ma][na][0], acc[ma][na][1]);
                *(float2*)(Cf + (r + 8) * N + c) = make_float2(acc[ma][na][2], acc[ma][na][3]);
            }
        }
    }
}

// ============================================================
// RoPE on half data, in place, with optional scale.
// t: [B*S, H, 64] half = 32 words/rowhead. Thread handles words w, w+16.
// ============================================================
__global__ void rope_half(uint32_t* __restrict__ t, int total, int H, float scale)
{
    int idx = blockIdx.x * blockDim.x + threadIdx.x;
    if (idx >= total) return;
    int w  = idx & 15;
    int rh = idx >> 4;
    int s  = (rh / H) % SS;

    float ang0, ang1, c0, s0, c1, s1;
    ang0 = (float)s * powf(10000.0f, -(float)(2 * w) / 32.0f);
    ang1 = (float)s * powf(10000.0f, -(float)(2 * w + 1) / 32.0f);
    sincosf(ang0, &s0, &c0);
    sincosf(ang1, &s1, &c1);

    uint32_t* p = t + (size_t)rh * 32 + w;
    __half2 hx = *(__half2*)p;
    __half2 hy = *(__half2*)(p + 16);
    float2 x = __half22float2(hx);
    float2 y = __half22float2(hy);

    float ox0 = (x.x * c0 - y.x * s0) * scale;
    float oy0 = (y.x * c0 + x.x * s0) * scale;
    float ox1 = (x.y * c1 - y.y * s1) * scale;
    float oy1 = (y.y * c1 + x.y * s1) * scale;

    *p        = h2(ox0, ox1);
    *(p + 16) = h2(oy0, oy1);
}

// ============================================================
// FP16 flash attention, ldmatrix fragments, half I/O.
// grid: (S/64, NH, B); 128 threads (4 warps x 16 query rows).
// ============================================================
#define FSTR 36   // word stride for all flash smem tiles

__global__ __launch_bounds__(128) void flash_f16(
    const uint4* __restrict__ Q, const uint4* __restrict__ K,
    const uint4* __restrict__ V, uint32_t* __restrict__ O)
{
    __shared__ __align__(16) uint32_t sQ[64 * FSTR];
    __shared__ __align__(16) uint32_t sK[64 * FSTR];
    __shared__ __align__(16) uint32_t sV[64 * FSTR];
    __shared__ __align__(16) uint32_t sP[4 * 16 * FSTR];

    const int tid  = threadIdx.x;
    const int warp = tid >> 5;
    const int lane = tid & 31;
    const int lr   = lane >> 2;
    const int lc   = lane & 3;
    const int g    = lane >> 3;   // ldmatrix lane group
    const int r8   = lane & 7;
    const int gh   = g & 1;
    const int gv   = g >> 1;
    const int qtile = gridDim.x - 1 - blockIdx.x;
    const int qb   = qtile * 64;
    const int h    = blockIdx.y;
    const int b    = blockIdx.z;
    const int kvh  = h >> 2;

    const uint32_t sQa = (uint32_t)__cvta_generic_to_shared(sQ);
    const uint32_t sKa = (uint32_t)__cvta_generic_to_shared(sK);
    const uint32_t sVa = (uint32_t)__cvta_generic_to_shared(sV);
    const uint32_t sPa = (uint32_t)__cvta_generic_to_shared(sP);

    // stage Q (already scaled by rope): pure copy
    for (int i = tid; i < 512; i += 128) {
        int r = i >> 3, c = i & 7;
        *(uint4*)&sQ[r * FSTR + c * 4] = Q[((size_t)(b * SS + qb + r) * NH + h) * 8 + c];
    }
    __syncthreads();

    // Q a-fragments for this warp (kc = 16-feat chunk)
    uint32_t qf[4][4];
#pragma unroll
    for (int kc = 0; kc < 4; kc++) {
        uint32_t addr = sQa + ((warp * 16 + gh * 8 + r8) * FSTR + kc * 8 + gv * 4) * 4;
        ldsm4(qf[kc], addr);
    }

    float acc[8][4];
#pragma unroll
    for (int na = 0; na < 8; na++)
#pragma unroll
        for (int r = 0; r < 4; r++) acc[na][r] = 0.0f;
    float m_lo = -1e30f, m_hi = -1e30f, l_lo = 0.0f, l_hi = 0.0f;

    uint32_t* pw = sP + warp * 16 * FSTR;
    const uint32_t pwa = sPa + warp * 16 * FSTR * 4;

    for (int kt = 0; kt <= qtile; kt++) {
        __syncthreads();
        for (int i = tid; i < 512; i += 128) {
            int r = i >> 3, c = i & 7;
            size_t src = ((size_t)(b * SS + kt * 64 + r) * NKV + kvh) * 8 + c;
            *(uint4*)&sK[r * FSTR + c * 4] = K[src];
            *(uint4*)&sV[r * FSTR + c * 4] = V[src];
        }
        __syncthreads();

        // S = Q @ K^T
        float sc[8][4];
#pragma unroll
        for (int na = 0; na < 8; na++)
            sc[na][0] = sc[na][1] = sc[na][2] = sc[na][3] = 0.0f;
#pragma unroll
        for (int na2 = 0; na2 < 4; na2++) {
#pragma unroll
            for (int kc = 0; kc < 4; kc++) {
                uint32_t kd[4];
                uint32_t addr = sKa + ((na2 * 16 + gv * 8 + r8) * FSTR + kc * 8 + gh * 4) * 4;
                ldsm4(kd, addr);
                mma_f16(sc[2*na2],     qf[kc][0], qf[kc][1], qf[kc][2], qf[kc][3], kd[0], kd[1]);
                mma_f16(sc[2*na2 + 1], qf[kc][0], qf[kc][1], qf[kc][2], qf[kc][3], kd[2], kd[3]);
            }
        }

        if (kt == qtile) {   // diagonal causal mask
            int r0 = warp * 16 + lr;
            int r1 = r0 + 8;
#pragma unroll
            for (int na = 0; na < 8; na++) {
                int col = na * 8 + 2 * lc;
                if (col     > r0) sc[na][0] = -1e30f;
                if (col + 1 > r0) sc[na][1] = -1e30f;
                if (col     > r1) sc[na][2] = -1e30f;
                if (col + 1 > r1) sc[na][3] = -1e30f;
            }
        }

        // online softmax
        float rm_lo = -1e30f, rm_hi = -1e30f;
#pragma unroll
        for (int na = 0; na < 8; na++) {
            rm_lo = fmaxf(rm_lo, fmaxf(sc[na][0], sc[na][1]));
            rm_hi = fmaxf(rm_hi, fmaxf(sc[na][2], sc[na][3]));
        }
        rm_lo = fmaxf(rm_lo, __shfl_xor_sync(0xffffffff, rm_lo, 1));
        rm_lo = fmaxf(rm_lo, __shfl_xor_sync(0xffffffff, rm_lo, 2));
        rm_hi = fmaxf(rm_hi, __shfl_xor_sync(0xffffffff, rm_hi, 1));
        rm_hi = fmaxf(rm_hi, __shfl_xor_sync(0xffffffff, rm_hi, 2));

        float mn_lo = fmaxf(m_lo, rm_lo);
        float mn_hi = fmaxf(m_hi, rm_hi);
        float corr_lo = __expf(m_lo - mn_lo);
        float corr_hi = __expf(m_hi - mn_hi);
        m_lo = mn_lo; m_hi = mn_hi;

        float ps_lo = 0.0f, ps_hi = 0.0f;
#pragma unroll
        for (int na = 0; na < 8; na++) {
            float p0 = __expf(sc[na][0] - m_lo);
            float p1 = __expf(sc[na][1] - m_lo);
            float p2 = __expf(sc[na][2] - m_hi);
            float p3 = __expf(sc[na][3] - m_hi);
            ps_lo += p0 + p1;
            ps_hi += p2 + p3;
            pw[lr * FSTR + na * 4 + lc]       = h2(p0, p1);
            pw[(lr + 8) * FSTR + na * 4 + lc] = h2(p2, p3);
            acc[na][0] *= corr_lo; acc[na][1] *= corr_lo;
            acc[na][2] *= corr_hi; acc[na][3] *= corr_hi;
        }
        ps_lo += __shfl_xor_sync(0xffffffff, ps_lo, 1);
        ps_lo += __shfl_xor_sync(0xffffffff, ps_lo, 2);
        ps_hi += __shfl_xor_sync(0xffffffff, ps_hi, 1);
        ps_hi += __shfl_xor_sync(0xffffffff, ps_hi, 2);
        l_lo = l_lo * corr_lo + ps_lo;
        l_hi = l_hi * corr_hi + ps_hi;

        __syncwarp();

        // O += P @ V  (P a-frags via ldmatrix, V b-frags via ldmatrix.trans)
#pragma unroll
        for (int kc = 0; kc < 4; kc++) {
            uint32_t pf[4];
            ldsm4(pf, pwa + ((gh * 8 + r8) * FSTR + kc * 8 + gv * 4) * 4);
#pragma unroll
            for (int na2 = 0; na2 < 4; na2++) {
                uint32_t vd[4];
                uint32_t addr = sVa + ((kc * 16 + gh * 8 + r8) * FSTR + na2 * 8 + gv * 4) * 4;
                ldsm4t(vd, addr);
                mma_f16(acc[2*na2],     pf[0], pf[1], pf[2], pf[3], vd[0], vd[1]);
                mma_f16(acc[2*na2 + 1], pf[0], pf[1], pf[2], pf[3], vd[2], vd[3]);
            }
        }
    }

    float inv_lo = 1.0f / l_lo;
    float inv_hi = 1.0f / l_hi;
    size_t r0 = (size_t)(b * SS + qb + warp * 16 + lr);
    size_t r1 = r0 + 8;
#pragma unroll
    for (int na = 0; na < 8; na++) {
        int wd = na * 4 + lc;
        O[(r0 * NH + h) * 32 + wd] = h2(acc[na][0] * inv_lo, acc[na][1] * inv_lo);
        O[(r1 * NH + h) * 32 + wd] = h2(acc[na][2] * inv_hi, acc[na][3] * inv_hi);
    }
}

// ============================================================
// launch
// ============================================================
extern "C" void kernel_launch(void* const* d_in, const int* in_sizes, int n_in,
                              void* d_out, int out_size)
{
    const float* x  = (const float*)d_in[0];
    const float* Wq = (const float*)d_in[1];
    const float* Wk = (const float*)d_in[2];
    const float* Wv = (const float*)d_in[3];
    const float* Wo = (const float*)d_in[4];
    float* out = (float*)d_out;

    void *q, *k, *v, *ctx;
    cudaGetSymbolAddress(&q,   g_q);
    cudaGetSymbolAddress(&k,   g_k);
    cudaGetSymbolAddress(&v,   g_v);
    cudaGetSymbolAddress(&ctx, g_ctx);

    const int M = BB * SS;  // 8192

    gemm_f16k<false, true><<<dim3((NH * DK) / 128, M / 128), 256>>>(x, Wq, q, M, NH * DK, DD);
    gemm_f16k<false, true><<<dim3((NKV * DK) / 128, M / 128), 256>>>(x, Wk, k, M, NKV * DK, DD);
    gemm_f16k<false, true><<<dim3((NKV * DK) / 128, M / 128), 256>>>(x, Wv, v, M, NKV * DK, DD);

    {
        int nq = M * NH * 16;
        rope_half<<<(nq + 255) / 256, 256>>>((uint32_t*)q, nq, NH, 0.125f);
        int nk = M * NKV * 16;
        rope_half<<<(nk + 255) / 256, 256>>>((uint32_t*)k, nk, NKV, 1.0f);
    }

    flash_f16<<<dim3(SS / 64, NH, BB), 128>>>(
        (const uint4*)q, (const uint4*)k, (const uint4*)v, (uint32_t*)ctx);

    gemm_f16k<true, false><<<dim3(DD / 128, M / 128), 256>>>(ctx, Wo, out, M, DD, DD);
}

// round 6
// speedup vs baseline: 5.3514x; 1.0679x over previous
#include <cuda_runtime.h>
#include <cuda_fp16.h>
#include <math.h>
#include <stdint.h>

#define BB   4
#define SS   2048
#define DD   1024
#define NH   16
#define NKV  4
#define DK   64

// -------- scratch (half-precision intermediates, uint4-aligned) --------
__device__ uint4 g_q[BB * SS * NH * DK / 8];
__device__ uint4 g_k[BB * SS * NKV * DK / 8];
__device__ uint4 g_v[BB * SS * NKV * DK / 8];
__device__ uint4 g_ctx[BB * SS * DD / 8];

__device__ __forceinline__ uint32_t h2(float a, float b) {
    __half2 h = __floats2half2_rn(a, b);
    return *(uint32_t*)&h;
}
__device__ __forceinline__ void mma_f16(float c[4],
    uint32_t a0, uint32_t a1, uint32_t a2, uint32_t a3,
    uint32_t b0, uint32_t b1)
{
    asm volatile(
        "mma.sync.aligned.m16n8k16.row.col.f32.f16.f16.f32 "
        "{%0,%1,%2,%3}, {%4,%5,%6,%7}, {%8,%9}, {%0,%1,%2,%3};\n"
        : "+f"(c[0]), "+f"(c[1]), "+f"(c[2]), "+f"(c[3])
        : "r"(a0), "r"(a1), "r"(a2), "r"(a3), "r"(b0), "r"(b1));
}
__device__ __forceinline__ void ldsm4(uint32_t d[4], uint32_t saddr) {
    asm volatile("ldmatrix.sync.aligned.m8n8.x4.shared.b16 {%0,%1,%2,%3}, [%4];\n"
        : "=r"(d[0]), "=r"(d[1]), "=r"(d[2]), "=r"(d[3]) : "r"(saddr));
}
__device__ __forceinline__ void ldsm4t(uint32_t d[4], uint32_t saddr) {
    asm volatile("ldmatrix.sync.aligned.m8n8.x4.trans.shared.b16 {%0,%1,%2,%3}, [%4];\n"
        : "=r"(d[0]), "=r"(d[1]), "=r"(d[2]), "=r"(d[3]) : "r"(saddr));
}
#define CP16(dst, src) \
    asm volatile("cp.async.cg.shared.global [%0], [%1], 16;\n" :: "r"(dst), "l"(src))
#define CP_COMMIT()  asm volatile("cp.async.commit_group;\n" ::)
#define CP_WAIT0()   asm volatile("cp.async.wait_group 0;\n" ::)
#define CP_WAIT1()   asm volatile("cp.async.wait_group 1;\n" ::)

// ============================================================
// FP16 tensor-core GEMM body: C[M,N] = A[M,K] @ B[K,N]
// 128x128x32 tiles, 256 threads, warp tile 64x32 (m16n8k16)
// ============================================================
#define GA_STR 20
#define GB_STR 136

template<bool AH, bool CH>
__device__ __forceinline__ void gemm_body(
    const void* __restrict__ Av, const float* __restrict__ B,
    void* __restrict__ Cv, int M, int N, int K)
{
    __shared__ __align__(16) uint32_t As2[128 * GA_STR];
    __shared__ __align__(16) uint32_t Bs2[16 * GB_STR];

    const int tid  = threadIdx.x;
    const int warp = tid >> 5;
    const int lane = tid & 31;
    const int lr   = lane >> 2;
    const int lc   = lane & 3;
    const int wrow = (warp & 1) * 64;
    const int wcol = (warp >> 1) * 32;
    const long rowBase = (long)blockIdx.y * 128;
    const long colBase = (long)blockIdx.x * 128;

    const int arow = tid >> 1;
    const int ahalf = tid & 1;
    const int bk   = tid >> 4;
    const int bc   = (tid & 15) * 8;

    const float* Aptr  = AH ? nullptr : (const float*)Av + (rowBase + arow) * (long)K + ahalf * 16;
    const uint4* Aptr4 = AH ? (const uint4*)Av + (rowBase + arow) * (long)(K / 8) + ahalf * 2 : nullptr;
    const float* Bptr0 = B + (long)(2 * bk) * N + colBase + bc;
    const float* Bptr1 = Bptr0 + N;

    float acc[4][4][4];
#pragma unroll
    for (int i = 0; i < 4; i++)
#pragma unroll
        for (int j = 0; j < 4; j++)
#pragma unroll
            for (int r = 0; r < 4; r++) acc[i][j][r] = 0.0f;

    float4 ra[4];
    uint4  ua[2];
    float4 rb0[2], rb1[2];

    if (AH) { ua[0] = Aptr4[0]; ua[1] = Aptr4[1]; }
    else {
#pragma unroll
        for (int i = 0; i < 4; i++) ra[i] = *(const float4*)(Aptr + i * 4);
    }
    rb0[0] = *(const float4*)(Bptr0);     rb0[1] = *(const float4*)(Bptr0 + 4);
    rb1[0] = *(const float4*)(Bptr1);     rb1[1] = *(const float4*)(Bptr1 + 4);

    {
        int wb = arow * GA_STR + ahalf * 8;
        if (AH) {
            *(uint4*)&As2[wb]     = ua[0];
            *(uint4*)&As2[wb + 4] = ua[1];
        } else {
            uint32_t wA[8];
#pragma unroll
            for (int i = 0; i < 4; i++) {
                wA[2*i]   = h2(ra[i].x, ra[i].y);
                wA[2*i+1] = h2(ra[i].z, ra[i].w);
            }
            *(uint4*)&As2[wb]     = make_uint4(wA[0], wA[1], wA[2], wA[3]);
            *(uint4*)&As2[wb + 4] = make_uint4(wA[4], wA[5], wA[6], wA[7]);
        }
        uint32_t wB[8];
#pragma unroll
        for (int i = 0; i < 2; i++) {
            const float* p0 = (const float*)&rb0[i];
            const float* p1 = (const float*)&rb1[i];
#pragma unroll
            for (int f = 0; f < 4; f++) wB[i*4+f] = h2(p0[f], p1[f]);
        }
        int wbb = bk * GB_STR + bc;
        *(uint4*)&Bs2[wbb]     = make_uint4(wB[0], wB[1], wB[2], wB[3]);
        *(uint4*)&Bs2[wbb + 4] = make_uint4(wB[4], wB[5], wB[6], wB[7]);
    }
    __syncthreads();

    for (int k0 = 32;; k0 += 32) {
        const bool more = (k0 < K);
        if (more) {
            if (AH) { ua[0] = Aptr4[k0 / 8]; ua[1] = Aptr4[k0 / 8 + 1]; }
            else {
#pragma unroll
                for (int i = 0; i < 4; i++) ra[i] = *(const float4*)(Aptr + k0 + i * 4);
            }
            rb0[0] = *(const float4*)(Bptr0 + (long)k0 * N);
            rb0[1] = *(const float4*)(Bptr0 + (long)k0 * N + 4);
            rb1[0] = *(const float4*)(Bptr1 + (long)k0 * N);
            rb1[1] = *(const float4*)(Bptr1 + (long)k0 * N + 4);
        }

#pragma unroll
        for (int kc = 0; kc < 2; kc++) {
            const int base = kc * 8;
            uint32_t a[4][4], b[4][2];
#pragma unroll
            for (int ma = 0; ma < 4; ma++) {
                int r = wrow + ma * 16 + lr;
                a[ma][0] = As2[r * GA_STR + base + lc];
                a[ma][1] = As2[(r + 8) * GA_STR + base + lc];
                a[ma][2] = As2[r * GA_STR + base + lc + 4];
                a[ma][3] = As2[(r + 8) * GA_STR + base + lc + 4];
            }
#pragma unroll
            for (int na = 0; na < 4; na++) {
                int c = wcol + na * 8 + lr;
                b[na][0] = Bs2[(base + lc) * GB_STR + c];
                b[na][1] = Bs2[(base + lc + 4) * GB_STR + c];
            }
#pragma unroll
            for (int ma = 0; ma < 4; ma++)
#pragma unroll
                for (int na = 0; na < 4; na++)
                    mma_f16(acc[ma][na], a[ma][0], a[ma][1], a[ma][2], a[ma][3],
                            b[na][0], b[na][1]);
        }

        if (!more) break;
        __syncthreads();
        {
            int wb = arow * GA_STR + ahalf * 8;
            if (AH) {
                *(uint4*)&As2[wb]     = ua[0];
                *(uint4*)&As2[wb + 4] = ua[1];
            } else {
                uint32_t wA[8];
#pragma unroll
                for (int i = 0; i < 4; i++) {
                    wA[2*i]   = h2(ra[i].x, ra[i].y);
                    wA[2*i+1] = h2(ra[i].z, ra[i].w);
                }
                *(uint4*)&As2[wb]     = make_uint4(wA[0], wA[1], wA[2], wA[3]);
                *(uint4*)&As2[wb + 4] = make_uint4(wA[4], wA[5], wA[6], wA[7]);
            }
            uint32_t wB[8];
#pragma unroll
            for (int i = 0; i < 2; i++) {
                const float* p0 = (const float*)&rb0[i];
                const float* p1 = (const float*)&rb1[i];
#pragma unroll
                for (int f = 0; f < 4; f++) wB[i*4+f] = h2(p0[f], p1[f]);
            }
            int wbb = bk * GB_STR + bc;
            *(uint4*)&Bs2[wbb]     = make_uint4(wB[0], wB[1], wB[2], wB[3]);
            *(uint4*)&Bs2[wbb + 4] = make_uint4(wB[4], wB[5], wB[6], wB[7]);
        }
        __syncthreads();
    }

#pragma unroll
    for (int ma = 0; ma < 4; ma++) {
#pragma unroll
        for (int na = 0; na < 4; na++) {
            long r = rowBase + wrow + ma * 16 + lr;
            long c = colBase + wcol + na * 8 + 2 * lc;
            if (CH) {
                uint32_t* Ch = (uint32_t*)Cv;
                Ch[(r * N + c) >> 1]       = h2(acc[ma][na][0], acc[ma][na][1]);
                Ch[((r + 8) * N + c) >> 1] = h2(acc[ma][na][2], acc[ma][na][3]);
            } else {
                float* Cf = (float*)Cv;
                *(float2*)(Cf + r * N + c)       = make_float2(acc[ma][na][0], acc[ma][na][1]);
                *(float2*)(Cf + (r + 8) * N + c) = make_float2(acc[ma][na][2], acc[ma][na][3]);
            }
        }
    }
}

template<bool AH, bool CH>
__global__ __launch_bounds__(256) void gemm_single(
    const void* __restrict__ A, const float* __restrict__ B,
    void* __restrict__ C, int M, int N, int K)
{
    gemm_body<AH, CH>(A, B, C, M, N, K);
}

// fused K/V projection: blockIdx.z selects (Wk->k) or (Wv->v)
__global__ __launch_bounds__(256) void gemm_kv(
    const float* __restrict__ A,
    const float* __restrict__ B0, const float* __restrict__ B1,
    void* __restrict__ C0, void* __restrict__ C1, int M, int N, int K)
{
    gemm_body<false, true>(A, blockIdx.z ? B1 : B0,
                           blockIdx.z ? C1 : C0, M, N, K);
}

// ============================================================
// Fused RoPE on half data for q and k, in place.
// ============================================================
__global__ void rope_both(uint32_t* __restrict__ q, uint32_t* __restrict__ k,
                          int nq, int nk)
{
    int idx = blockIdx.x * blockDim.x + threadIdx.x;
    if (idx >= nq + nk) return;
    uint32_t* t; int H; float scale; int j;
    if (idx < nq) { t = q; H = NH;  scale = 0.125f; j = idx; }
    else          { t = k; H = NKV; scale = 1.0f;   j = idx - nq; }

    int w  = j & 15;
    int rh = j >> 4;
    int s  = (rh / H) % SS;

    float ang0 = (float)s * powf(10000.0f, -(float)(2 * w) / 32.0f);
    float ang1 = (float)s * powf(10000.0f, -(float)(2 * w + 1) / 32.0f);
    float c0, s0, c1, s1;
    sincosf(ang0, &s0, &c0);
    sincosf(ang1, &s1, &c1);

    uint32_t* p = t + (size_t)rh * 32 + w;
    float2 x = __half22float2(*(__half2*)p);
    float2 y = __half22float2(*(__half2*)(p + 16));

    *p        = h2((x.x * c0 - y.x * s0) * scale, (x.y * c1 - y.y * s1) * scale);
    *(p + 16) = h2((y.x * c0 + x.x * s0) * scale, (y.y * c1 + x.y * s1) * scale);
}

// ============================================================
// FP16 flash attention: 128-q tiles, 256 threads (8 warps x 16 rows),
// 64-key tiles, cp.async double-buffered KV, causal warp-skip.
// ============================================================
#define FSTR 36
#define FLASH_SMEM ((128 + 128 + 4 * 64) * FSTR * 4)   // sQ + sP + 2x(K+V)

__global__ __launch_bounds__(256) void flash_f16(
    const uint4* __restrict__ Q, const uint4* __restrict__ K,
    const uint4* __restrict__ V, uint32_t* __restrict__ O)
{
    extern __shared__ __align__(16) uint32_t dsm[];
    uint32_t* sQ   = dsm;                      // 128 rows
    uint32_t* sP   = sQ + 128 * FSTR;          // 128 rows (8 warps x 16)
    uint32_t* sKV0 = sP + 128 * FSTR;          // K 64 rows | V 64 rows
    uint32_t* sKV1 = sKV0 + 128 * FSTR;

    const int tid  = threadIdx.x;
    const int warp = tid >> 5;
    const int lane = tid & 31;
    const int lr   = lane >> 2;
    const int lc   = lane & 3;
    const int g    = lane >> 3;
    const int r8   = lane & 7;
    const int gh   = g & 1;
    const int gv   = g >> 1;
    const int qt   = gridDim.x - 1 - blockIdx.x;   // longest first
    const int qb   = qt * 128;
    const int h    = blockIdx.y;
    const int b    = blockIdx.z;
    const int kvh  = h >> 2;
    const int ntiles = 2 * qt + 2;

    const uint32_t sQa   = (uint32_t)__cvta_generic_to_shared(sQ);
    const uint32_t sPa   = (uint32_t)__cvta_generic_to_shared(sP);
    const uint32_t sKV0a = (uint32_t)__cvta_generic_to_shared(sKV0);
    const uint32_t sKV1a = (uint32_t)__cvta_generic_to_shared(sKV1);

    // KV staging via cp.async: 1024 16B chunks (512 K + 512 V), 4/thread
    const int si  = tid;                // chunk ids si, si+256, si+512, si+768
    auto stageKV = [&](int kt, uint32_t bufa) {
#pragma unroll
        for (int u = 0; u < 4; u++) {
            int i   = si + u * 256;
            int idx = i & 511;
            int r   = idx >> 3, c = idx & 7;
            const uint4* src = ((i < 512) ? K : V) +
                ((size_t)(b * SS + kt * 64 + r) * NKV + kvh) * 8 + c;
            uint32_t dst = bufa + (((i < 512) ? 0 : 64 * FSTR) + r * FSTR + c * 4) * 4;
            CP16(dst, src);
        }
        CP_COMMIT();
    };

    // stage Q (pre-scaled by rope): plain copy, 1024 chunks
    for (int i = tid; i < 1024; i += 256) {
        int r = i >> 3, c = i & 7;
        *(uint4*)&sQ[r * FSTR + c * 4] = Q[((size_t)(b * SS + qb + r) * NH + h) * 8 + c];
    }

    // prologue: stage KV tile 0
    stageKV(0, sKV0a);
    __syncthreads();

    uint32_t qf[4][4];
#pragma unroll
    for (int kc = 0; kc < 4; kc++)
        ldsm4(qf[kc], sQa + ((warp * 16 + gh * 8 + r8) * FSTR + kc * 8 + gv * 4) * 4);

    float acc[8][4];
#pragma unroll
    for (int na = 0; na < 8; na++)
#pragma unroll
        for (int r = 0; r < 4; r++) acc[na][r] = 0.0f;
    float m_lo = -1e30f, m_hi = -1e30f, l_lo = 0.0f, l_hi = 0.0f;

    uint32_t* pw = sP + warp * 16 * FSTR;
    const uint32_t pwa = sPa + warp * 16 * FSTR * 4;
    const int wr_lo = warp * 16;

    for (int kt = 0; kt < ntiles; kt++) {
        const uint32_t cura = (kt & 1) ? sKV1a : sKV0a;
        const uint32_t curK = cura;
        const uint32_t curV = cura + 64 * FSTR * 4;

        if (kt + 1 < ntiles) {
            stageKV(kt + 1, (kt & 1) ? sKV0a : sKV1a);
            CP_WAIT1();
        } else {
            CP_WAIT0();
        }
        __syncthreads();

        const int rel = wr_lo - kt * 64 + qb - qb;  // local; keys tile-local
        const int relq = qb + wr_lo - kt * 64;
        if (relq + 15 >= 0) {   // not fully masked for this warp
            // S = Q @ K^T
            float sc[8][4];
#pragma unroll
            for (int na = 0; na < 8; na++)
                sc[na][0] = sc[na][1] = sc[na][2] = sc[na][3] = 0.0f;
#pragma unroll
            for (int na2 = 0; na2 < 4; na2++) {
#pragma unroll
                for (int kc = 0; kc < 4; kc++) {
                    uint32_t kd[4];
                    ldsm4(kd, curK + ((na2 * 16 + gv * 8 + r8) * FSTR + kc * 8 + gh * 4) * 4);
                    mma_f16(sc[2*na2],     qf[kc][0], qf[kc][1], qf[kc][2], qf[kc][3], kd[0], kd[1]);
                    mma_f16(sc[2*na2 + 1], qf[kc][0], qf[kc][1], qf[kc][2], qf[kc][3], kd[2], kd[3]);
                }
            }

            if (relq < 63) {    // partial diagonal tile: elementwise mask
#pragma unroll
                for (int na = 0; na < 8; na++) {
                    int col = na * 8 + 2 * lc;
                    if (col     > relq + lr)     sc[na][0] = -1e30f;
                    if (col + 1 > relq + lr)     sc[na][1] = -1e30f;
                    if (col     > relq + lr + 8) sc[na][2] = -1e30f;
                    if (col + 1 > relq + lr + 8) sc[na][3] = -1e30f;
                }
            }

            // online softmax
            float rm_lo = -1e30f, rm_hi = -1e30f;
#pragma unroll
            for (int na = 0; na < 8; na++) {
                rm_lo = fmaxf(rm_lo, fmaxf(sc[na][0], sc[na][1]));
                rm_hi = fmaxf(rm_hi, fmaxf(sc[na][2], sc[na][3]));
            }
            rm_lo = fmaxf(rm_lo, __shfl_xor_sync(0xffffffff, rm_lo, 1));
            rm_lo = fmaxf(rm_lo, __shfl_xor_sync(0xffffffff, rm_lo, 2));
            rm_hi = fmaxf(rm_hi, __shfl_xor_sync(0xffffffff, rm_hi, 1));
            rm_hi = fmaxf(rm_hi, __shfl_xor_sync(0xffffffff, rm_hi, 2));

            float mn_lo = fmaxf(m_lo, rm_lo);
            float mn_hi = fmaxf(m_hi, rm_hi);
            float corr_lo = __expf(m_lo - mn_lo);
            float corr_hi = __expf(m_hi - mn_hi);
            m_lo = mn_lo; m_hi = mn_hi;

            float ps_lo = 0.0f, ps_hi = 0.0f;
#pragma unroll
            for (int na = 0; na < 8; na++) {
                float p0 = __expf(sc[na][0] - m_lo);
                float p1 = __expf(sc[na][1] - m_lo);
                float p2 = __expf(sc[na][2] - m_hi);
                float p3 = __expf(sc[na][3] - m_hi);
                ps_lo += p0 + p1;
                ps_hi += p2 + p3;
                pw[lr * FSTR + na * 4 + lc]       = h2(p0, p1);
                pw[(lr + 8) * FSTR + na * 4 + lc] = h2(p2, p3);
                acc[na][0] *= corr_lo; acc[na][1] *= corr_lo;
                acc[na][2] *= corr_hi; acc[na][3] *= corr_hi;
            }
            ps_lo += __shfl_xor_sync(0xffffffff, ps_lo, 1);
            ps_lo += __shfl_xor_sync(0xffffffff, ps_lo, 2);
            ps_hi += __shfl_xor_sync(0xffffffff, ps_hi, 1);
            ps_hi += __shfl_xor_sync(0xffffffff, ps_hi, 2);
            l_lo = l_lo * corr_lo + ps_lo;
            l_hi = l_hi * corr_hi + ps_hi;

            __syncwarp();

            // O += P @ V
#pragma unroll
            for (int kc = 0; kc < 4; kc++) {
                uint32_t pf[4];
                ldsm4(pf, pwa + ((gh * 8 + r8) * FSTR + kc * 8 + gv * 4) * 4);
#pragma unroll
                for (int na2 = 0; na2 < 4; na2++) {
                    uint32_t vd[4];
                    ldsm4t(vd, curV + ((kc * 16 + gh * 8 + r8) * FSTR + na2 * 8 + gv * 4) * 4);
                    mma_f16(acc[2*na2],     pf[0], pf[1], pf[2], pf[3], vd[0], vd[1]);
                    mma_f16(acc[2*na2 + 1], pf[0], pf[1], pf[2], pf[3], vd[2], vd[3]);
                }
            }
        }
        __syncthreads();   // all warps done reading cur before it is restaged
        (void)rel;
    }

    float inv_lo = 1.0f / l_lo;
    float inv_hi = 1.0f / l_hi;
    size_t r0 = (size_t)(b * SS + qb + warp * 16 + lr);
    size_t r1 = r0 + 8;
#pragma unroll
    for (int na = 0; na < 8; na++) {
        int wd = na * 4 + lc;
        O[(r0 * NH + h) * 32 + wd] = h2(acc[na][0] * inv_lo, acc[na][1] * inv_lo);
        O[(r1 * NH + h) * 32 + wd] = h2(acc[na][2] * inv_hi, acc[na][3] * inv_hi);
    }
}

// ============================================================
// launch
// ============================================================
extern "C" void kernel_launch(void* const* d_in, const int* in_sizes, int n_in,
                              void* d_out, int out_size)
{
    const float* x  = (const float*)d_in[0];
    const float* Wq = (const float*)d_in[1];
    const float* Wk = (const float*)d_in[2];
    const float* Wv = (const float*)d_in[3];
    const float* Wo = (const float*)d_in[4];
    float* out = (float*)d_out;

    void *q, *k, *v, *ctx;
    cudaGetSymbolAddress(&q,   g_q);
    cudaGetSymbolAddress(&k,   g_k);
    cudaGetSymbolAddress(&v,   g_v);
    cudaGetSymbolAddress(&ctx, g_ctx);

    const int M = BB * SS;  // 8192

    gemm_single<false, true><<<dim3((NH * DK) / 128, M / 128), 256>>>(
        x, Wq, q, M, NH * DK, DD);
    gemm_kv<<<dim3((NKV * DK) / 128, M / 128, 2), 256>>>(
        x, Wk, Wv, k, v, M, NKV * DK, DD);

    {
        int nq = M * NH * 16;
        int nk = M * NKV * 16;
        rope_both<<<(nq + nk + 255) / 256, 256>>>((uint32_t*)q, (uint32_t*)k, nq, nk);
    }

    cudaFuncSetAttribute(flash_f16, cudaFuncAttributeMaxDynamicSharedMemorySize, FLASH_SMEM);
    flash_f16<<<dim3(SS / 128, NH, BB), 256, FLASH_SMEM>>>(
        (const uint4*)q, (const uint4*)k, (const uint4*)v, (uint32_t*)ctx);

    gemm_single<true, false><<<dim3(DD / 128, M / 128), 256>>>(
        ctx, Wo, out, M, DD, DD);
}

// round 7
// speedup vs baseline: 6.0760x; 1.1354x over previous
#include <cuda_runtime.h>
#include <cuda_fp16.h>
#include <math.h>
#include <stdint.h>

#define BB   4
#define SS   2048
#define DD   1024
#define NH   16
#define NKV  4
#define DK   64

// -------- scratch (no allocations allowed) --------
__device__ uint4 g_q[BB * SS * NH * DK / 8];
__device__ uint4 g_k[BB * SS * NKV * DK / 8];
__device__ uint4 g_v[BB * SS * NKV * DK / 8];
__device__ uint4 g_ctx[BB * SS * DD / 8];
__device__ uint4 g_xh[BB * SS * DD / 8];          // x in half
__device__ uint4 g_wqkvT[1536 * 1024 / 8];        // [Wq|Wk|Wv]^T half, [N,K]
__device__ uint4 g_woT[1024 * 1024 / 8];          // Wo^T half, [N,K]

__device__ __forceinline__ uint32_t h2(float a, float b) {
    __half2 h = __floats2half2_rn(a, b);
    return *(uint32_t*)&h;
}
__device__ __forceinline__ void mma_f16(float c[4],
    uint32_t a0, uint32_t a1, uint32_t a2, uint32_t a3,
    uint32_t b0, uint32_t b1)
{
    asm volatile(
        "mma.sync.aligned.m16n8k16.row.col.f32.f16.f16.f32 "
        "{%0,%1,%2,%3}, {%4,%5,%6,%7}, {%8,%9}, {%0,%1,%2,%3};\n"
        : "+f"(c[0]), "+f"(c[1]), "+f"(c[2]), "+f"(c[3])
        : "r"(a0), "r"(a1), "r"(a2), "r"(a3), "r"(b0), "r"(b1));
}
__device__ __forceinline__ void ldsm4(uint32_t d[4], uint32_t saddr) {
    asm volatile("ldmatrix.sync.aligned.m8n8.x4.shared.b16 {%0,%1,%2,%3}, [%4];\n"
        : "=r"(d[0]), "=r"(d[1]), "=r"(d[2]), "=r"(d[3]) : "r"(saddr));
}
__device__ __forceinline__ void ldsm4t(uint32_t d[4], uint32_t saddr) {
    asm volatile("ldmatrix.sync.aligned.m8n8.x4.trans.shared.b16 {%0,%1,%2,%3}, [%4];\n"
        : "=r"(d[0]), "=r"(d[1]), "=r"(d[2]), "=r"(d[3]) : "r"(saddr));
}
#define CP16(dst, src) \
    asm volatile("cp.async.cg.shared.global [%0], [%1], 16;\n" :: "r"(dst), "l"(src))
#define CP_COMMIT()  asm volatile("cp.async.commit_group;\n" ::)
#define CP_WAIT0()   asm volatile("cp.async.wait_group 0;\n" ::)
#define CP_WAIT1()   asm volatile("cp.async.wait_group 1;\n" ::)

// ============================================================
// convert x (f32 -> f16), elementwise
// ============================================================
__global__ void convert_x(const float4* __restrict__ x, uint2* __restrict__ xh, int n4)
{
    int i = blockIdx.x * blockDim.x + threadIdx.x;
    if (i >= n4) return;
    float4 t = x[i];
    xh[i] = make_uint2(h2(t.x, t.y), h2(t.z, t.w));
}

// ============================================================
// transpose weights f32 [K=1024, C] -> half [C, 1024]
// z: 0=Wq(C=1024) 1=Wk(256) 2=Wv(256) 3=Wo(1024)
// ============================================================
__global__ void transpose_w(const float* __restrict__ Wq, const float* __restrict__ Wk,
                            const float* __restrict__ Wv, const float* __restrict__ Wo,
                            __half* __restrict__ wqkvT, __half* __restrict__ woT)
{
    __shared__ float tile[32][33];
    const int z = blockIdx.z;
    const float* src; __half* dst; int C;
    if      (z == 0) { src = Wq; dst = wqkvT;               C = 1024; }
    else if (z == 1) { src = Wk; dst = wqkvT + 1024 * 1024; C = 256;  }
    else if (z == 2) { src = Wv; dst = wqkvT + 1280 * 1024; C = 256;  }
    else             { src = Wo; dst = woT;                 C = 1024; }

    int c0 = blockIdx.x * 32;
    if (c0 >= C) return;
    int r0 = blockIdx.y * 32;
    int tx = threadIdx.x, ty = threadIdx.y;

#pragma unroll
    for (int i = 0; i < 4; i++)
        tile[ty + i * 8][tx] = src[(size_t)(r0 + ty + i * 8) * C + c0 + tx];
    __syncthreads();
#pragma unroll
    for (int i = 0; i < 4; i++)
        dst[(size_t)(c0 + ty + i * 8) * 1024 + r0 + tx] =
            __float2half_rn(tile[tx][ty + i * 8]);
}

// ============================================================
// All-half GEMM: C[M,N] = A[M,K] @ Bt[N,K]^T
// 128x128x32 tiles, 256 threads (8 warps, warp tile 32x64),
// cp.async 3-stage pipeline, ldmatrix fragments.
// MODE 0: half output split into q/k/v by column. MODE 1: float out.
// ============================================================
#define GSTR 20
#define G_AWORDS (128 * GSTR)
#define G_STAGE_WORDS (2 * G_AWORDS)
#define G_STAGES 3
#define GEMM_SMEM (G_STAGES * G_STAGE_WORDS * 4)

template<int MODE>
__global__ __launch_bounds__(256, 2) void gemm_h(
    const uint4* __restrict__ A4, const uint4* __restrict__ B4,
    uint32_t* __restrict__ qp, uint32_t* __restrict__ kp, uint32_t* __restrict__ vp,
    float* __restrict__ outp, int K, int KT)
{
    extern __shared__ __align__(16) uint32_t gsm[];
    const uint32_t smA = (uint32_t)__cvta_generic_to_shared(gsm);

    const int tid  = threadIdx.x;
    const int warp = tid >> 5;
    const int lane = tid & 31;
    const int lr   = lane >> 2;
    const int lc   = lane & 3;
    const int g    = lane >> 3;
    const int r8   = lane & 7;
    const int gh   = g & 1;
    const int gv   = g >> 1;
    const int wrow = (warp & 3) * 32;
    const int wcol = (warp >> 2) * 64;
    const long rowBase = (long)blockIdx.y * 128;
    const long colBase = (long)blockIdx.x * 128;

    // loader: threads 0-127 -> A rows, 128-255 -> B rows; 64B per thread
    const int lrow = tid & 127;
    const uint4* srcBase = (tid < 128)
        ? A4 + (size_t)(rowBase + lrow) * (K >> 3)
        : B4 + (size_t)(colBase + lrow) * (K >> 3);
    const uint32_t dstw = (tid < 128 ? 0 : G_AWORDS) + lrow * GSTR;

    float acc[2][8][4];
#pragma unroll
    for (int i = 0; i < 2; i++)
#pragma unroll
        for (int j = 0; j < 8; j++)
#pragma unroll
            for (int r = 0; r < 4; r++) acc[i][j][r] = 0.0f;

    // prologue: stages 0, 1
#pragma unroll
    for (int s = 0; s < G_STAGES - 1; s++) {
        uint32_t base = smA + (s * G_STAGE_WORDS + dstw) * 4;
#pragma unroll
        for (int ch = 0; ch < 4; ch++)
            CP16(base + ch * 16, srcBase + s * 4 + ch);
        CP_COMMIT();
    }

    for (int kt = 0; kt < KT; kt++) {
        CP_WAIT1();
        __syncthreads();

        // issue stage kt + STAGES-1
        if (kt + G_STAGES - 1 < KT) {
            int s = (kt + G_STAGES - 1) % G_STAGES;
            uint32_t base = smA + (s * G_STAGE_WORDS + dstw) * 4;
#pragma unroll
            for (int ch = 0; ch < 4; ch++)
                CP16(base + ch * 16, srcBase + (kt + G_STAGES - 1) * 4 + ch);
        }
        CP_COMMIT();

        const uint32_t curA = smA + (kt % G_STAGES) * G_STAGE_WORDS * 4;
        const uint32_t curB = curA + G_AWORDS * 4;

#pragma unroll
        for (int kc = 0; kc < 2; kc++) {
            uint32_t af[2][4];
#pragma unroll
            for (int ma = 0; ma < 2; ma++)
                ldsm4(af[ma], curA + ((wrow + ma * 16 + gh * 8 + r8) * GSTR + kc * 8 + gv * 4) * 4);
#pragma unroll
            for (int na2 = 0; na2 < 4; na2++) {
                uint32_t bd[4];
                ldsm4(bd, curB + ((wcol + na2 * 16 + gv * 8 + r8) * GSTR + kc * 8 + gh * 4) * 4);
#pragma unroll
                for (int ma = 0; ma < 2; ma++) {
                    mma_f16(acc[ma][2 * na2],     af[ma][0], af[ma][1], af[ma][2], af[ma][3], bd[0], bd[1]);
                    mma_f16(acc[ma][2 * na2 + 1], af[ma][0], af[ma][1], af[ma][2], af[ma][3], bd[2], bd[3]);
                }
            }
        }
    }

    // epilogue
    if (MODE == 0) {
        uint32_t* T; int tstride, toff;
        if (colBase < 1024)      { T = qp; tstride = 1024; toff = (int)colBase; }
        else if (colBase < 1280) { T = kp; tstride = 256;  toff = (int)colBase - 1024; }
        else                     { T = vp; tstride = 256;  toff = (int)colBase - 1280; }
#pragma unroll
        for (int ma = 0; ma < 2; ma++) {
            long r0 = rowBase + wrow + ma * 16 + lr;
#pragma unroll
            for (int na = 0; na < 8; na++) {
                int col = toff + wcol + na * 8 + 2 * lc;
                T[(r0 * tstride + col) >> 1]       = h2(acc[ma][na][0], acc[ma][na][1]);
                T[((r0 + 8) * tstride + col) >> 1] = h2(acc[ma][na][2], acc[ma][na][3]);
            }
        }
    } else {
#pragma unroll
        for (int ma = 0; ma < 2; ma++) {
            long r0 = rowBase + wrow + ma * 16 + lr;
#pragma unroll
            for (int na = 0; na < 8; na++) {
                int col = (int)colBase + wcol + na * 8 + 2 * lc;
                *(float2*)(outp + r0 * DD + col) =
                    make_float2(acc[ma][na][0], acc[ma][na][1]);
                *(float2*)(outp + (r0 + 8) * DD + col) =
                    make_float2(acc[ma][na][2], acc[ma][na][3]);
            }
        }
    }
}

// ============================================================
// Fused RoPE on half q and k, in place.
// ============================================================
__global__ void rope_both(uint32_t* __restrict__ q, uint32_t* __restrict__ k,
                          int nq, int nk)
{
    int idx = blockIdx.x * blockDim.x + threadIdx.x;
    if (idx >= nq + nk) return;
    uint32_t* t; int H; float scale; int j;
    if (idx < nq) { t = q; H = NH;  scale = 0.125f; j = idx; }
    else          { t = k; H = NKV; scale = 1.0f;   j = idx - nq; }

    int w  = j & 15;
    int rh = j >> 4;
    int s  = (rh / H) % SS;

    float ang0 = (float)s * powf(10000.0f, -(float)(2 * w) / 32.0f);
    float ang1 = (float)s * powf(10000.0f, -(float)(2 * w + 1) / 32.0f);
    float c0, s0, c1, s1;
    sincosf(ang0, &s0, &c0);
    sincosf(ang1, &s1, &c1);

    uint32_t* p = t + (size_t)rh * 32 + w;
    float2 x = __half22float2(*(__half2*)p);
    float2 y = __half22float2(*(__half2*)(p + 16));

    *p        = h2((x.x * c0 - y.x * s0) * scale, (x.y * c1 - y.y * s1) * scale);
    *(p + 16) = h2((y.x * c0 + x.x * s0) * scale, (y.y * c1 + x.y * s1) * scale);
}

// ============================================================
// FP16 flash attention: 128-q tiles, 256 threads (8 warps x 16 rows),
// 64-key tiles, cp.async double-buffered KV, causal warp-skip.
// ============================================================
#define FSTR 36
#define FLASH_SMEM ((128 + 128 + 4 * 64) * FSTR * 4)

__global__ __launch_bounds__(256) void flash_f16(
    const uint4* __restrict__ Q, const uint4* __restrict__ K,
    const uint4* __restrict__ V, uint32_t* __restrict__ O)
{
    extern __shared__ __align__(16) uint32_t dsm[];
    uint32_t* sQ   = dsm;
    uint32_t* sP   = sQ + 128 * FSTR;
    uint32_t* sKV0 = sP + 128 * FSTR;
    uint32_t* sKV1 = sKV0 + 128 * FSTR;

    const int tid  = threadIdx.x;
    const int warp = tid >> 5;
    const int lane = tid & 31;
    const int lr   = lane >> 2;
    const int lc   = lane & 3;
    const int g    = lane >> 3;
    const int r8   = lane & 7;
    const int gh   = g & 1;
    const int gv   = g >> 1;
    const int qt   = gridDim.x - 1 - blockIdx.x;
    const int qb   = qt * 128;
    const int h    = blockIdx.y;
    const int b    = blockIdx.z;
    const int kvh  = h >> 2;
    const int ntiles = 2 * qt + 2;

    const uint32_t sQa   = (uint32_t)__cvta_generic_to_shared(sQ);
    const uint32_t sPa   = (uint32_t)__cvta_generic_to_shared(sP);
    const uint32_t sKV0a = (uint32_t)__cvta_generic_to_shared(sKV0);
    const uint32_t sKV1a = (uint32_t)__cvta_generic_to_shared(sKV1);

    const int si = tid;
    auto stageKV = [&](int kt, uint32_t bufa) {
#pragma unroll
        for (int u = 0; u < 4; u++) {
            int i   = si + u * 256;
            int idx = i & 511;
            int r   = idx >> 3, c = idx & 7;
            const uint4* src = ((i < 512) ? K : V) +
                ((size_t)(b * SS + kt * 64 + r) * NKV + kvh) * 8 + c;
            uint32_t dst = bufa + (((i < 512) ? 0 : 64 * FSTR) + r * FSTR + c * 4) * 4;
            CP16(dst, src);
        }
        CP_COMMIT();
    };

    for (int i = tid; i < 1024; i += 256) {
        int r = i >> 3, c = i & 7;
        *(uint4*)&sQ[r * FSTR + c * 4] = Q[((size_t)(b * SS + qb + r) * NH + h) * 8 + c];
    }

    stageKV(0, sKV0a);
    __syncthreads();

    uint32_t qf[4][4];
#pragma unroll
    for (int kc = 0; kc < 4; kc++)
        ldsm4(qf[kc], sQa + ((warp * 16 + gh * 8 + r8) * FSTR + kc * 8 + gv * 4) * 4);

    float acc[8][4];
#pragma unroll
    for (int na = 0; na < 8; na++)
#pragma unroll
        for (int r = 0; r < 4; r++) acc[na][r] = 0.0f;
    float m_lo = -1e30f, m_hi = -1e30f, l_lo = 0.0f, l_hi = 0.0f;

    uint32_t* pw = sP + warp * 16 * FSTR;
    const uint32_t pwa = sPa + warp * 16 * FSTR * 4;
    const int wr_lo = warp * 16;

    for (int kt = 0; kt < ntiles; kt++) {
        const uint32_t cura = (kt & 1) ? sKV1a : sKV0a;
        const uint32_t curK = cura;
        const uint32_t curV = cura + 64 * FSTR * 4;

        if (kt + 1 < ntiles) {
            stageKV(kt + 1, (kt & 1) ? sKV0a : sKV1a);
            CP_WAIT1();
        } else {
            CP_WAIT0();
        }
        __syncthreads();

        const int relq = qb + wr_lo - kt * 64;
        if (relq + 15 >= 0) {
            float sc[8][4];
#pragma unroll
            for (int na = 0; na < 8; na++)
                sc[na][0] = sc[na][1] = sc[na][2] = sc[na][3] = 0.0f;
#pragma unroll
            for (int na2 = 0; na2 < 4; na2++) {
#pragma unroll
                for (int kc = 0; kc < 4; kc++) {
                    uint32_t kd[4];
                    ldsm4(kd, curK + ((na2 * 16 + gv * 8 + r8) * FSTR + kc * 8 + gh * 4) * 4);
                    mma_f16(sc[2*na2],     qf[kc][0], qf[kc][1], qf[kc][2], qf[kc][3], kd[0], kd[1]);
                    mma_f16(sc[2*na2 + 1], qf[kc][0], qf[kc][1], qf[kc][2], qf[kc][3], kd[2], kd[3]);
                }
            }

            if (relq < 63) {
#pragma unroll
                for (int na = 0; na < 8; na++) {
                    int col = na * 8 + 2 * lc;
                    if (col     > relq + lr)     sc[na][0] = -1e30f;
                    if (col + 1 > relq + lr)     sc[na][1] = -1e30f;
                    if (col     > relq + lr + 8) sc[na][2] = -1e30f;
                    if (col + 1 > relq + lr + 8) sc[na][3] = -1e30f;
                }
            }

            float rm_lo = -1e30f, rm_hi = -1e30f;
#pragma unroll
            for (int na = 0; na < 8; na++) {
                rm_lo = fmaxf(rm_lo, fmaxf(sc[na][0], sc[na][1]));
                rm_hi = fmaxf(rm_hi, fmaxf(sc[na][2], sc[na][3]));
            }
            rm_lo = fmaxf(rm_lo, __shfl_xor_sync(0xffffffff, rm_lo, 1));
            rm_lo = fmaxf(rm_lo, __shfl_xor_sync(0xffffffff, rm_lo, 2));
            rm_hi = fmaxf(rm_hi, __shfl_xor_sync(0xffffffff, rm_hi, 1));
            rm_hi = fmaxf(rm_hi, __shfl_xor_sync(0xffffffff, rm_hi, 2));

            float mn_lo = fmaxf(m_lo, rm_lo);
            float mn_hi = fmaxf(m_hi, rm_hi);
            float corr_lo = __expf(m_lo - mn_lo);
            float corr_hi = __expf(m_hi - mn_hi);
            m_lo = mn_lo; m_hi = mn_hi;

            float ps_lo = 0.0f, ps_hi = 0.0f;
#pragma unroll
            for (int na = 0; na < 8; na++) {
                float p0 = __expf(sc[na][0] - m_lo);
                float p1 = __expf(sc[na][1] - m_lo);
                float p2 = __expf(sc[na][2] - m_hi);
                float p3 = __expf(sc[na][3] - m_hi);
                ps_lo += p0 + p1;
                ps_hi += p2 + p3;
                pw[lr * FSTR + na * 4 + lc]       = h2(p0, p1);
                pw[(lr + 8) * FSTR + na * 4 + lc] = h2(p2, p3);
                acc[na][0] *= corr_lo; acc[na][1] *= corr_lo;
                acc[na][2] *= corr_hi; acc[na][3] *= corr_hi;
            }
            ps_lo += __shfl_xor_sync(0xffffffff, ps_lo, 1);
            ps_lo += __shfl_xor_sync(0xffffffff, ps_lo, 2);
            ps_hi += __shfl_xor_sync(0xffffffff, ps_hi, 1);
            ps_hi += __shfl_xor_sync(0xffffffff, ps_hi, 2);
            l_lo = l_lo * corr_lo + ps_lo;
            l_hi = l_hi * corr_hi + ps_hi;

            __syncwarp();

#pragma unroll
            for (int kc = 0; kc < 4; kc++) {
                uint32_t pf[4];
                ldsm4(pf, pwa + ((gh * 8 + r8) * FSTR + kc * 8 + gv * 4) * 4);
#pragma unroll
                for (int na2 = 0; na2 < 4; na2++) {
                    uint32_t vd[4];
                    ldsm4t(vd, curV + ((kc * 16 + gh * 8 + r8) * FSTR + na2 * 8 + gv * 4) * 4);
                    mma_f16(acc[2*na2],     pf[0], pf[1], pf[2], pf[3], vd[0], vd[1]);
                    mma_f16(acc[2*na2 + 1], pf[0], pf[1], pf[2], pf[3], vd[2], vd[3]);
                }
            }
        }
        __syncthreads();
    }

    float inv_lo = 1.0f / l_lo;
    float inv_hi = 1.0f / l_hi;
    size_t r0 = (size_t)(b * SS + qb + warp * 16 + lr);
    size_t r1 = r0 + 8;
#pragma unroll
    for (int na = 0; na < 8; na++) {
        int wd = na * 4 + lc;
        O[(r0 * NH + h) * 32 + wd] = h2(acc[na][0] * inv_lo, acc[na][1] * inv_lo);
        O[(r1 * NH + h) * 32 + wd] = h2(acc[na][2] * inv_hi, acc[na][3] * inv_hi);
    }
}

// ============================================================
// launch
// ============================================================
extern "C" void kernel_launch(void* const* d_in, const int* in_sizes, int n_in,
                              void* d_out, int out_size)
{
    const float* x  = (const float*)d_in[0];
    const float* Wq = (const float*)d_in[1];
    const float* Wk = (const float*)d_in[2];
    const float* Wv = (const float*)d_in[3];
    const float* Wo = (const float*)d_in[4];
    float* out = (float*)d_out;

    void *q, *k, *v, *ctx, *xh, *wqkvT, *woT;
    cudaGetSymbolAddress(&q,     g_q);
    cudaGetSymbolAddress(&k,     g_k);
    cudaGetSymbolAddress(&v,     g_v);
    cudaGetSymbolAddress(&ctx,   g_ctx);
    cudaGetSymbolAddress(&xh,    g_xh);
    cudaGetSymbolAddress(&wqkvT, g_wqkvT);
    cudaGetSymbolAddress(&woT,   g_woT);

    const int M = BB * SS;  // 8192

    cudaFuncSetAttribute(gemm_h<0>, cudaFuncAttributeMaxDynamicSharedMemorySize, GEMM_SMEM);
    cudaFuncSetAttribute(gemm_h<1>, cudaFuncAttributeMaxDynamicSharedMemorySize, GEMM_SMEM);
    cudaFuncSetAttribute(flash_f16, cudaFuncAttributeMaxDynamicSharedMemorySize, FLASH_SMEM);

    // convert x to half
    convert_x<<<(M * DD / 4 + 255) / 256, 256>>>(
        (const float4*)x, (uint2*)xh, M * DD / 4);
    // transpose + convert weights
    transpose_w<<<dim3(32, 32, 4), dim3(32, 8)>>>(
        Wq, Wk, Wv, Wo, (__half*)wqkvT, (__half*)woT);

    // fused QKV projection
    gemm_h<0><<<dim3(12, M / 128), 256, GEMM_SMEM>>>(
        (const uint4*)xh, (const uint4*)wqkvT,
        (uint32_t*)q, (uint32_t*)k, (uint32_t*)v, nullptr, DD, DD / 32);

    // RoPE
    {
        int nq = M * NH * 16;
        int nk = M * NKV * 16;
        rope_both<<<(nq + nk + 255) / 256, 256>>>((uint32_t*)q, (uint32_t*)k, nq, nk);
    }

    // attention
    flash_f16<<<dim3(SS / 128, NH, BB), 256, FLASH_SMEM>>>(
        (const uint4*)q, (const uint4*)k, (const uint4*)v, (uint32_t*)ctx);

    // output projection
    gemm_h<1><<<dim3(8, M / 128), 256, GEMM_SMEM>>>(
        (const uint4*)ctx, (const uint4*)woT,
        nullptr, nullptr, nullptr, out, DD, DD / 32);
}

// round 8
// speedup vs baseline: 6.1337x; 1.0095x over previous
#include <cuda_runtime.h>
#include <cuda_fp16.h>
#include <math.h>
#include <stdint.h>

#define BB   4
#define SS   2048
#define DD   1024
#define NH   16
#define NKV  4
#define DK   64

// -------- scratch (no allocations allowed) --------
__device__ uint4 g_q[BB * SS * NH * DK / 8];
__device__ uint4 g_k[BB * SS * NKV * DK / 8];
__device__ uint4 g_v[BB * SS * NKV * DK / 8];
__device__ uint4 g_ctx[BB * SS * DD / 8];
__device__ uint4 g_xh[BB * SS * DD / 8];          // x in half
__device__ uint4 g_wqkvT[1536 * 1024 / 8];        // [Wq|Wk|Wv]^T half, [N,K]
__device__ uint4 g_woT[1024 * 1024 / 8];          // Wo^T half, [N,K]
__device__ float g_cosT[SS * 32];                 // rope tables
__device__ float g_sinT[SS * 32];

__device__ __forceinline__ uint32_t h2(float a, float b) {
    __half2 h = __floats2half2_rn(a, b);
    return *(uint32_t*)&h;
}
__device__ __forceinline__ void mma_f16(float c[4],
    uint32_t a0, uint32_t a1, uint32_t a2, uint32_t a3,
    uint32_t b0, uint32_t b1)
{
    asm volatile(
        "mma.sync.aligned.m16n8k16.row.col.f32.f16.f16.f32 "
        "{%0,%1,%2,%3}, {%4,%5,%6,%7}, {%8,%9}, {%0,%1,%2,%3};\n"
        : "+f"(c[0]), "+f"(c[1]), "+f"(c[2]), "+f"(c[3])
        : "r"(a0), "r"(a1), "r"(a2), "r"(a3), "r"(b0), "r"(b1));
}
__device__ __forceinline__ void ldsm4(uint32_t d[4], uint32_t saddr) {
    asm volatile("ldmatrix.sync.aligned.m8n8.x4.shared.b16 {%0,%1,%2,%3}, [%4];\n"
        : "=r"(d[0]), "=r"(d[1]), "=r"(d[2]), "=r"(d[3]) : "r"(saddr));
}
__device__ __forceinline__ void ldsm4t(uint32_t d[4], uint32_t saddr) {
    asm volatile("ldmatrix.sync.aligned.m8n8.x4.trans.shared.b16 {%0,%1,%2,%3}, [%4];\n"
        : "=r"(d[0]), "=r"(d[1]), "=r"(d[2]), "=r"(d[3]) : "r"(saddr));
}
#define CP16(dst, src) \
    asm volatile("cp.async.cg.shared.global [%0], [%1], 16;\n" :: "r"(dst), "l"(src))
#define CP_COMMIT()  asm volatile("cp.async.commit_group;\n" ::)
#define CP_WAIT0()   asm volatile("cp.async.wait_group 0;\n" ::)
#define CP_WAIT1()   asm volatile("cp.async.wait_group 1;\n" ::)

// ============================================================
// helpers: convert x, build rope tables, transpose weights
// ============================================================
__global__ void convert_x(const float4* __restrict__ x, uint2* __restrict__ xh, int n4)
{
    int i = blockIdx.x * blockDim.x + threadIdx.x;
    if (i >= n4) return;
    float4 t = x[i];
    xh[i] = make_uint2(h2(t.x, t.y), h2(t.z, t.w));
}

__global__ void build_cs()
{
    int i = blockIdx.x * blockDim.x + threadIdx.x;
    if (i >= SS * 32) return;
    int s = i >> 5, f = i & 31;
    float theta = powf(10000.0f, -(float)f / 32.0f);
    float sn, cs;
    sincosf((float)s * theta, &sn, &cs);
    g_cosT[i] = cs;
    g_sinT[i] = sn;
}

__global__ void transpose_w(const float* __restrict__ Wq, const float* __restrict__ Wk,
                            const float* __restrict__ Wv, const float* __restrict__ Wo,
                            __half* __restrict__ wqkvT, __half* __restrict__ woT)
{
    __shared__ float tile[32][33];
    const int z = blockIdx.z;
    const float* src; __half* dst; int C;
    if      (z == 0) { src = Wq; dst = wqkvT;               C = 1024; }
    else if (z == 1) { src = Wk; dst = wqkvT + 1024 * 1024; C = 256;  }
    else if (z == 2) { src = Wv; dst = wqkvT + 1280 * 1024; C = 256;  }
    else             { src = Wo; dst = woT;                 C = 1024; }

    int c0 = blockIdx.x * 32;
    if (c0 >= C) return;
    int r0 = blockIdx.y * 32;
    int tx = threadIdx.x, ty = threadIdx.y;

#pragma unroll
    for (int i = 0; i < 4; i++)
        tile[ty + i * 8][tx] = src[(size_t)(r0 + ty + i * 8) * C + c0 + tx];
    __syncthreads();
#pragma unroll
    for (int i = 0; i < 4; i++)
        dst[(size_t)(c0 + ty + i * 8) * 1024 + r0 + tx] =
            __float2half_rn(tile[tx][ty + i * 8]);
}

// ============================================================
// All-half GEMM: C[M,N] = A[M,K] @ Bt[N,K]^T
// 128x128x32 tiles, 256 threads (8 warps, warp tile 32x64),
// cp.async 3-stage pipeline, ldmatrix fragments.
// MODE 0: half qkv output, RoPE fused in epilogue. MODE 1: float out.
// ============================================================
#define GSTR 20
#define G_AWORDS (128 * GSTR)
#define G_STAGE_WORDS (2 * G_AWORDS)
#define G_STAGES 3
#define GEMM_SMEM (G_STAGES * G_STAGE_WORDS * 4)

template<int MODE>
__global__ __launch_bounds__(256, 2) void gemm_h(
    const uint4* __restrict__ A4, const uint4* __restrict__ B4,
    uint32_t* __restrict__ qp, uint32_t* __restrict__ kp, uint32_t* __restrict__ vp,
    float* __restrict__ outp, int K, int KT)
{
    extern __shared__ __align__(16) uint32_t gsm[];
    const uint32_t smA = (uint32_t)__cvta_generic_to_shared(gsm);

    const int tid  = threadIdx.x;
    const int warp = tid >> 5;
    const int lane = tid & 31;
    const int lr   = lane >> 2;
    const int lc   = lane & 3;
    const int g    = lane >> 3;
    const int r8   = lane & 7;
    const int gh   = g & 1;
    const int gv   = g >> 1;
    const int wrow = (warp & 3) * 32;
    const int wcol = (warp >> 2) * 64;
    const long rowBase = (long)blockIdx.y * 128;
    const long colBase = (long)blockIdx.x * 128;

    const int lrow = tid & 127;
    const uint4* srcBase = (tid < 128)
        ? A4 + (size_t)(rowBase + lrow) * (K >> 3)
        : B4 + (size_t)(colBase + lrow) * (K >> 3);
    const uint32_t dstw = (tid < 128 ? 0 : G_AWORDS) + lrow * GSTR;

    float acc[2][8][4];
#pragma unroll
    for (int i = 0; i < 2; i++)
#pragma unroll
        for (int j = 0; j < 8; j++)
#pragma unroll
            for (int r = 0; r < 4; r++) acc[i][j][r] = 0.0f;

#pragma unroll
    for (int s = 0; s < G_STAGES - 1; s++) {
        uint32_t base = smA + (s * G_STAGE_WORDS + dstw) * 4;
#pragma unroll
        for (int ch = 0; ch < 4; ch++)
            CP16(base + ch * 16, srcBase + s * 4 + ch);
        CP_COMMIT();
    }

    for (int kt = 0; kt < KT; kt++) {
        CP_WAIT1();
        __syncthreads();

        if (kt + G_STAGES - 1 < KT) {
            int s = (kt + G_STAGES - 1) % G_STAGES;
            uint32_t base = smA + (s * G_STAGE_WORDS + dstw) * 4;
#pragma unroll
            for (int ch = 0; ch < 4; ch++)
                CP16(base + ch * 16, srcBase + (kt + G_STAGES - 1) * 4 + ch);
        }
        CP_COMMIT();

        const uint32_t curA = smA + (kt % G_STAGES) * G_STAGE_WORDS * 4;
        const uint32_t curB = curA + G_AWORDS * 4;

#pragma unroll
        for (int kc = 0; kc < 2; kc++) {
            uint32_t af[2][4];
#pragma unroll
            for (int ma = 0; ma < 2; ma++)
                ldsm4(af[ma], curA + ((wrow + ma * 16 + gh * 8 + r8) * GSTR + kc * 8 + gv * 4) * 4);
#pragma unroll
            for (int na2 = 0; na2 < 4; na2++) {
                uint32_t bd[4];
                ldsm4(bd, curB + ((wcol + na2 * 16 + gv * 8 + r8) * GSTR + kc * 8 + gh * 4) * 4);
#pragma unroll
                for (int ma = 0; ma < 2; ma++) {
                    mma_f16(acc[ma][2 * na2],     af[ma][0], af[ma][1], af[ma][2], af[ma][3], bd[0], bd[1]);
                    mma_f16(acc[ma][2 * na2 + 1], af[ma][0], af[ma][1], af[ma][2], af[ma][3], bd[2], bd[3]);
                }
            }
        }
    }

    // epilogue
    if (MODE == 0) {
        uint32_t* T; int tstride, toff;
        if (colBase < 1024)      { T = qp; tstride = 1024; toff = (int)colBase; }
        else if (colBase < 1280) { T = kp; tstride = 256;  toff = (int)colBase - 1024; }
        else                     { T = vp; tstride = 256;  toff = (int)colBase - 1280; }
        const bool  doRope = (colBase < 1280);
        const float qscale = (colBase < 1024) ? 0.125f : 1.0f;

#pragma unroll
        for (int ma = 0; ma < 2; ma++) {
            long r0 = rowBase + wrow + ma * 16 + lr;
            if (doRope) {
                int s0 = (int)(r0 & (SS - 1));
                int s1 = (int)((r0 + 8) & (SS - 1));
#pragma unroll
                for (int na = 0; na < 4; na++) {
                    int f = na * 8 + 2 * lc;
                    float2 c0 = *(const float2*)(g_cosT + s0 * 32 + f);
                    float2 n0 = *(const float2*)(g_sinT + s0 * 32 + f);
                    float2 c1 = *(const float2*)(g_cosT + s1 * 32 + f);
                    float2 n1 = *(const float2*)(g_sinT + s1 * 32 + f);
                    float x0 = acc[ma][na][0], x1 = acc[ma][na][1];
                    float y0 = acc[ma][na + 4][0], y1 = acc[ma][na + 4][1];
                    acc[ma][na][0]     = x0 * c0.x - y0 * n0.x;
                    acc[ma][na + 4][0] = y0 * c0.x + x0 * n0.x;
                    acc[ma][na][1]     = x1 * c0.y - y1 * n0.y;
                    acc[ma][na + 4][1] = y1 * c0.y + x1 * n0.y;
                    float x2 = acc[ma][na][2], x3 = acc[ma][na][3];
                    float y2 = acc[ma][na + 4][2], y3 = acc[ma][na + 4][3];
                    acc[ma][na][2]     = x2 * c1.x - y2 * n1.x;
                    acc[ma][na + 4][2] = y2 * c1.x + x2 * n1.x;
                    acc[ma][na][3]     = x3 * c1.y - y3 * n1.y;
                    acc[ma][na + 4][3] = y3 * c1.y + x3 * n1.y;
                }
            }
#pragma unroll
            for (int na = 0; na < 8; na++) {
                int col = toff + wcol + na * 8 + 2 * lc;
                T[(r0 * tstride + col) >> 1] =
                    h2(acc[ma][na][0] * qscale, acc[ma][na][1] * qscale);
                T[((r0 + 8) * tstride + col) >> 1] =
                    h2(acc[ma][na][2] * qscale, acc[ma][na][3] * qscale);
            }
        }
    } else {
#pragma unroll
        for (int ma = 0; ma < 2; ma++) {
            long r0 = rowBase + wrow + ma * 16 + lr;
#pragma unroll
            for (int na = 0; na < 8; na++) {
                int col = (int)colBase + wcol + na * 8 + 2 * lc;
                *(float2*)(outp + r0 * DD + col) =
                    make_float2(acc[ma][na][0], acc[ma][na][1]);
                *(float2*)(outp + (r0 + 8) * DD + col) =
                    make_float2(acc[ma][na][2], acc[ma][na][3]);
            }
        }
    }
}

// ============================================================
// FP16 flash attention: 128-q tiles, 256 threads (8 warps x 16 rows),
// 64-key tiles, cp.async triple-buffered KV, ONE sync per tile.
// ============================================================
#define FSTR 36
#define FLASH_SMEM ((128 + 128 + 3 * 128) * FSTR * 4)

__global__ __launch_bounds__(256) void flash_f16(
    const uint4* __restrict__ Q, const uint4* __restrict__ K,
    const uint4* __restrict__ V, uint32_t* __restrict__ O)
{
    extern __shared__ __align__(16) uint32_t dsm[];
    uint32_t* sQ  = dsm;
    uint32_t* sP  = sQ + 128 * FSTR;
    uint32_t* sKV = sP + 128 * FSTR;     // 3 buffers x (64 K rows + 64 V rows)

    const int tid  = threadIdx.x;
    const int warp = tid >> 5;
    const int lane = tid & 31;
    const int lr   = lane >> 2;
    const int lc   = lane & 3;
    const int g    = lane >> 3;
    const int r8   = lane & 7;
    const int gh   = g & 1;
    const int gv   = g >> 1;
    const int qt   = gridDim.x - 1 - blockIdx.x;
    const int qb   = qt * 128;
    const int h    = blockIdx.y;
    const int b    = blockIdx.z;
    const int kvh  = h >> 2;
    const int ntiles = 2 * qt + 2;

    const uint32_t sQa  = (uint32_t)__cvta_generic_to_shared(sQ);
    const uint32_t sPa  = (uint32_t)__cvta_generic_to_shared(sP);
    const uint32_t sKVa = (uint32_t)__cvta_generic_to_shared(sKV);

    const int si = tid;
    auto stageKV = [&](int kt, int buf) {
        uint32_t bufa = sKVa + buf * 128 * FSTR * 4;
#pragma unroll
        for (int u = 0; u < 4; u++) {
            int i   = si + u * 256;
            int idx = i & 511;
            int r   = idx >> 3, c = idx & 7;
            const uint4* src = ((i < 512) ? K : V) +
                ((size_t)(b * SS + kt * 64 + r) * NKV + kvh) * 8 + c;
            uint32_t dst = bufa + (((i < 512) ? 0 : 64 * FSTR) + r * FSTR + c * 4) * 4;
            CP16(dst, src);
        }
        CP_COMMIT();
    };

    for (int i = tid; i < 1024; i += 256) {
        int r = i >> 3, c = i & 7;
        *(uint4*)&sQ[r * FSTR + c * 4] = Q[((size_t)(b * SS + qb + r) * NH + h) * 8 + c];
    }

    stageKV(0, 0);
    stageKV(1, 1);

    // first sync arrives inside loop iteration 0

    float acc[8][4];
#pragma unroll
    for (int na = 0; na < 8; na++)
#pragma unroll
        for (int r = 0; r < 4; r++) acc[na][r] = 0.0f;
    float m_lo = -1e30f, m_hi = -1e30f, l_lo = 0.0f, l_hi = 0.0f;

    uint32_t* pw = sP + warp * 16 * FSTR;
    const uint32_t pwa = sPa + warp * 16 * FSTR * 4;
    const int wr_lo = warp * 16;
    uint32_t qf[4][4];
    bool qloaded = false;

    for (int kt = 0; kt < ntiles; kt++) {
        if (kt + 1 < ntiles) CP_WAIT1(); else CP_WAIT0();
        __syncthreads();
        if (kt + 2 < ntiles) stageKV(kt + 2, (kt + 2) % 3);

        if (!qloaded) {   // after first sync: Q smem is visible
            qloaded = true;
#pragma unroll
            for (int kc = 0; kc < 4; kc++)
                ldsm4(qf[kc], sQa + ((warp * 16 + gh * 8 + r8) * FSTR + kc * 8 + gv * 4) * 4);
        }

        const uint32_t cura = sKVa + (kt % 3) * 128 * FSTR * 4;
        const uint32_t curK = cura;
        const uint32_t curV = cura + 64 * FSTR * 4;

        const int relq = qb + wr_lo - kt * 64;
        if (relq + 15 >= 0) {
            float sc[8][4];
#pragma unroll
            for (int na = 0; na < 8; na++)
                sc[na][0] = sc[na][1] = sc[na][2] = sc[na][3] = 0.0f;
#pragma unroll
            for (int na2 = 0; na2 < 4; na2++) {
#pragma unroll
                for (int kc = 0; kc < 4; kc++) {
                    uint32_t kd[4];
                    ldsm4(kd, curK + ((na2 * 16 + gv * 8 + r8) * FSTR + kc * 8 + gh * 4) * 4);
                    mma_f16(sc[2*na2],     qf[kc][0], qf[kc][1], qf[kc][2], qf[kc][3], kd[0], kd[1]);
                    mma_f16(sc[2*na2 + 1], qf[kc][0], qf[kc][1], qf[kc][2], qf[kc][3], kd[2], kd[3]);
                }
            }

            if (relq < 63) {
#pragma unroll
                for (int na = 0; na < 8; na++) {
                    int col = na * 8 + 2 * lc;
                    if (col     > relq + lr)     sc[na][0] = -1e30f;
                    if (col + 1 > relq + lr)     sc[na][1] = -1e30f;
                    if (col     > relq + lr + 8) sc[na][2] = -1e30f;
                    if (col + 1 > relq + lr + 8) sc[na][3] = -1e30f;
                }
            }

            float rm_lo = -1e30f, rm_hi = -1e30f;
#pragma unroll
            for (int na = 0; na < 8; na++) {
                rm_lo = fmaxf(rm_lo, fmaxf(sc[na][0], sc[na][1]));
                rm_hi = fmaxf(rm_hi, fmaxf(sc[na][2], sc[na][3]));
            }
            rm_lo = fmaxf(rm_lo, __shfl_xor_sync(0xffffffff, rm_lo, 1));
            rm_lo = fmaxf(rm_lo, __shfl_xor_sync(0xffffffff, rm_lo, 2));
            rm_hi = fmaxf(rm_hi, __shfl_xor_sync(0xffffffff, rm_hi, 1));
            rm_hi = fmaxf(rm_hi, __shfl_xor_sync(0xffffffff, rm_hi, 2));

            float mn_lo = fmaxf(m_lo, rm_lo);
            float mn_hi = fmaxf(m_hi, rm_hi);
            float corr_lo = __expf(m_lo - mn_lo);
            float corr_hi = __expf(m_hi - mn_hi);
            m_lo = mn_lo; m_hi = mn_hi;

            float ps_lo = 0.0f, ps_hi = 0.0f;
#pragma unroll
            for (int na = 0; na < 8; na++) {
                float p0 = __expf(sc[na][0] - m_lo);
                float p1 = __expf(sc[na][1] - m_lo);
                float p2 = __expf(sc[na][2] - m_hi);
                float p3 = __expf(sc[na][3] - m_hi);
                ps_lo += p0 + p1;
                ps_hi += p2 + p3;
                pw[lr * FSTR + na * 4 + lc]       = h2(p0, p1);
                pw[(lr + 8) * FSTR + na * 4 + lc] = h2(p2, p3);
                acc[na][0] *= corr_lo; acc[na][1] *= corr_lo;
                acc[na][2] *= corr_hi; acc[na][3] *= corr_hi;
            }
            ps_lo += __shfl_xor_sync(0xffffffff, ps_lo, 1);
            ps_lo += __shfl_xor_sync(0xffffffff, ps_lo, 2);
            ps_hi += __shfl_xor_sync(0xffffffff, ps_hi, 1);
            ps_hi += __shfl_xor_sync(0xffffffff, ps_hi, 2);
            l_lo = l_lo * corr_lo + ps_lo;
            l_hi = l_hi * corr_hi + ps_hi;

            __syncwarp();

#pragma unroll
            for (int kc = 0; kc < 4; kc++) {
                uint32_t pf[4];
                ldsm4(pf, pwa + ((gh * 8 + r8) * FSTR + kc * 8 + gv * 4) * 4);
#pragma unroll
                for (int na2 = 0; na2 < 4; na2++) {
                    uint32_t vd[4];
                    ldsm4t(vd, curV + ((kc * 16 + gh * 8 + r8) * FSTR + na2 * 8 + gv * 4) * 4);
                    mma_f16(acc[2*na2],     pf[0], pf[1], pf[2], pf[3], vd[0], vd[1]);
                    mma_f16(acc[2*na2 + 1], pf[0], pf[1], pf[2], pf[3], vd[2], vd[3]);
                }
            }
        }
    }

    float inv_lo = 1.0f / l_lo;
    float inv_hi = 1.0f / l_hi;
    size_t r0 = (size_t)(b * SS + qb + warp * 16 + lr);
    size_t r1 = r0 + 8;
#pragma unroll
    for (int na = 0; na < 8; na++) {
        int wd = na * 4 + lc;
        O[(r0 * NH + h) * 32 + wd] = h2(acc[na][0] * inv_lo, acc[na][1] * inv_lo);
        O[(r1 * NH + h) * 32 + wd] = h2(acc[na][2] * inv_hi, acc[na][3] * inv_hi);
    }
}

// ============================================================
// launch
// ============================================================
extern "C" void kernel_launch(void* const* d_in, const int* in_sizes, int n_in,
                              void* d_out, int out_size)
{
    const float* x  = (const float*)d_in[0];
    const float* Wq = (const float*)d_in[1];
    const float* Wk = (const float*)d_in[2];
    const float* Wv = (const float*)d_in[3];
    const float* Wo = (const float*)d_in[4];
    float* out = (float*)d_out;

    void *q, *k, *v, *ctx, *xh, *wqkvT, *woT;
    cudaGetSymbolAddress(&q,     g_q);
    cudaGetSymbolAddress(&k,     g_k);
    cudaGetSymbolAddress(&v,     g_v);
    cudaGetSymbolAddress(&ctx,   g_ctx);
    cudaGetSymbolAddress(&xh,    g_xh);
    cudaGetSymbolAddress(&wqkvT, g_wqkvT);
    cudaGetSymbolAddress(&woT,   g_woT);

    const int M = BB * SS;  // 8192

    cudaFuncSetAttribute(gemm_h<0>, cudaFuncAttributeMaxDynamicSharedMemorySize, GEMM_SMEM);
    cudaFuncSetAttribute(gemm_h<1>, cudaFuncAttributeMaxDynamicSharedMemorySize, GEMM_SMEM);
    cudaFuncSetAttribute(flash_f16, cudaFuncAttributeMaxDynamicSharedMemorySize, FLASH_SMEM);

    convert_x<<<(M * DD / 4 + 255) / 256, 256>>>(
        (const float4*)x, (uint2*)xh, M * DD / 4);
    build_cs<<<(SS * 32 + 255) / 256, 256>>>();
    transpose_w<<<dim3(32, 32, 4), dim3(32, 8)>>>(
        Wq, Wk, Wv, Wo, (__half*)wqkvT, (__half*)woT);

    // fused QKV projection + RoPE
    gemm_h<0><<<dim3(12, M / 128), 256, GEMM_SMEM>>>(
        (const uint4*)xh, (const uint4*)wqkvT,
        (uint32_t*)q, (uint32_t*)k, (uint32_t*)v, nullptr, DD, DD / 32);

    // attention
    flash_f16<<<dim3(SS / 128, NH, BB), 256, FLASH_SMEM>>>(
        (const uint4*)q, (const uint4*)k, (const uint4*)v, (uint32_t*)ctx);

    // output projection
    gemm_h<1><<<dim3(8, M / 128), 256, GEMM_SMEM>>>(
        (const uint4*)ctx, (const uint4*)woT,
        nullptr, nullptr, nullptr, out, DD, DD / 32);
}